// round 2
// baseline (speedup 1.0000x reference)
#include <cuda_runtime.h>
#include <math.h>

#define NN 100000
#define EI 800000
#define EE 400000
#define HD 128
#define GB 256
#define ND 35
#define NBLK_SCAN 98   // ceil(100000/1024)

// ---------------- device scratch ----------------
__device__ float d_h [NN * HD];
__device__ float d_h2[NN * HD];
__device__ float d_vp[NN * HD];
__device__ float d_vl[NN * HD];
__device__ float d_wint[EE];
__device__ int   d_ecnt_i[NN];
__device__ int   d_ecnt_e[NN];
__device__ int   d_fill_i[NN];
__device__ int   d_fill_e[NN];
__device__ int   d_off_i[NN + 1];
__device__ int   d_off_e[NN + 1];
__device__ int   d_bsum_i[NBLK_SCAN];
__device__ int   d_bsum_e[NBLK_SCAN];
__device__ int   d_csrc_i[EI];
__device__ float d_cw_i[EI];
__device__ int   d_csrc_e[EE];
__device__ float d_cw_e[EE];
__device__ float d_cnti[NN];
__device__ float d_cnte[NN];
__device__ float d_invi[NN];
__device__ float d_loge[NN];
__device__ float d_pool[GB * HD];
__device__ float d_fcbuf[GB * HD];

// ---------------- helpers ----------------
__device__ __forceinline__ float siluf(float v) { return v / (1.0f + expf(-v)); }

__device__ __forceinline__ void red_add_v4(float* p, float4 v) {
    asm volatile("red.global.add.v4.f32 [%0], {%1,%2,%3,%4};"
                 :: "l"(p), "f"(v.x), "f"(v.y), "f"(v.z), "f"(v.w) : "memory");
}

__device__ __forceinline__ unsigned long long pk(float x, float y) {
    unsigned long long r;
    asm("mov.b64 %0, {%1, %2};" : "=l"(r) : "f"(x), "f"(y));
    return r;
}
__device__ __forceinline__ void unpk(unsigned long long v, float& lo, float& hi) {
    asm("mov.b64 {%0, %1}, %2;" : "=f"(lo), "=f"(hi) : "l"(v));
}
__device__ __forceinline__ void fma2(unsigned long long& d, unsigned long long a,
                                     unsigned long long b) {
    asm("fma.rn.f32x2 %0, %1, %2, %0;" : "+l"(d) : "l"(a), "l"(b));
}

// ---------------- init ----------------
__global__ void k_zero_pre() {
    int i = blockIdx.x * blockDim.x + threadIdx.x;
    if (i < NN) {
        d_ecnt_i[i] = 0; d_ecnt_e[i] = 0;
        d_fill_i[i] = 0; d_fill_e[i] = 0;
    }
    if (i < GB * HD) d_pool[i] = 0.0f;
}

// lin_node: h = silu(x @ W + b); vp = vl = 0
__global__ __launch_bounds__(128) void k_linnode(const float* __restrict__ x,
                                                 const float* __restrict__ W,
                                                 const float* __restrict__ b) {
    __shared__ float Ws[ND * HD];
    __shared__ float xs[8][ND];
    int t = threadIdx.x;
    for (int i = t; i < ND * HD; i += 128) Ws[i] = W[i];
    int n0 = blockIdx.x * 8;
    for (int i = t; i < 8 * ND; i += 128) {
        int nn = i / ND, k = i % ND;
        xs[nn][k] = x[(n0 + nn) * ND + k];
    }
    __syncthreads();
    float bb = b[t];
    for (int nn = 0; nn < 8; nn++) {
        int n = n0 + nn;
        float acc = bb;
#pragma unroll
        for (int k = 0; k < ND; k++) acc += xs[nn][k] * Ws[k * HD + t];
        d_h[n * HD + t] = siluf(acc);
        d_vp[n * HD + t] = 0.0f;
        d_vl[n * HD + t] = 0.0f;
    }
}

// ---------------- degree counting + geometric weights ----------------
__global__ void k_deg_intra(const int* __restrict__ ei) {
    int e = blockIdx.x * blockDim.x + threadIdx.x;
    if (e < EI) atomicAdd(&d_ecnt_i[ei[EI + e]], 1);
}

__global__ void k_deg_inter(const int* __restrict__ ee, const float* __restrict__ pos) {
    int e = blockIdx.x * blockDim.x + threadIdx.x;
    if (e < EE) {
        int s = ee[e], d = ee[EE + e];
        float dx = pos[s * 3 + 0] - pos[d * 3 + 0];
        float dy = pos[s * 3 + 1] - pos[d * 3 + 1];
        float dz = pos[s * 3 + 2] - pos[d * 3 + 2];
        d_wint[e] = expf(-(dx * dx + dy * dy + dz * dz));
        atomicAdd(&d_ecnt_e[d], 1);
    }
}

// ---------------- prefix scan (exclusive) over counts -> CSR offsets ----------------
__global__ __launch_bounds__(1024) void k_scan_a(int which) {
    __shared__ int sh[1024];
    const int* cnt = which ? d_ecnt_e : d_ecnt_i;
    int* off = which ? d_off_e : d_off_i;
    int* bs  = which ? d_bsum_e : d_bsum_i;
    int tid = threadIdx.x;
    int i = blockIdx.x * 1024 + tid;
    int v = (i < NN) ? cnt[i] : 0;
    sh[tid] = v;
    __syncthreads();
#pragma unroll
    for (int o = 1; o < 1024; o <<= 1) {
        int u = (tid >= o) ? sh[tid - o] : 0;
        __syncthreads();
        sh[tid] += u;
        __syncthreads();
    }
    if (i <= NN) off[i] = sh[tid] - v;  // exclusive
    if (tid == 1023) bs[blockIdx.x] = sh[1023];
}

__global__ void k_scan_b() {
    if (threadIdx.x == 0) {
        int r = 0;
        for (int b = 0; b < NBLK_SCAN; b++) { int t = d_bsum_i[b]; d_bsum_i[b] = r; r += t; }
    }
    if (threadIdx.x == 1) {
        int r = 0;
        for (int b = 0; b < NBLK_SCAN; b++) { int t = d_bsum_e[b]; d_bsum_e[b] = r; r += t; }
    }
}

__global__ __launch_bounds__(1024) void k_scan_c(int which) {
    int* off = which ? d_off_e : d_off_i;
    const int* bs = which ? d_bsum_e : d_bsum_i;
    int i = blockIdx.x * 1024 + threadIdx.x;
    if (i <= NN) off[i] += bs[blockIdx.x];
}

__global__ void k_factors() {
    int n = blockIdx.x * blockDim.x + threadIdx.x;
    if (n < NN) {
        float ci = (float)d_ecnt_i[n];
        float ce = (float)d_ecnt_e[n];
        d_cnti[n] = ci;
        d_cnte[n] = ce;
        d_invi[n] = 1.0f / (ci + 1.0f);
        d_loge[n] = logf(ce + 1.0f);
    }
}

// ---------------- CSR fill ----------------
__global__ void k_fill_i(const int* __restrict__ ei, const float* __restrict__ ea) {
    int e = blockIdx.x * blockDim.x + threadIdx.x;
    if (e < EI) {
        int s = ei[e], d = ei[EI + e];
        int p = d_off_i[d] + atomicAdd(&d_fill_i[d], 1);
        d_csrc_i[p] = s;
        d_cw_i[p] = ea[e];
    }
}

__global__ void k_fill_e(const int* __restrict__ ee) {
    int e = blockIdx.x * blockDim.x + threadIdx.x;
    if (e < EE) {
        int s = ee[e], d = ee[EE + e];
        int p = d_off_e[d] + atomicAdd(&d_fill_e[d], 1);
        d_csrc_e[p] = s;
        d_cw_e[p] = d_wint[e];
    }
}

// ---------------- fused layer: CSR gather + dual GEMM (f32x2) + SiLU update ----------------
// block = 32 nodes, 256 threads. Dynamic smem:
//   Ai (dup f32x2) 32x128, Ae (dup) 32x128, Wsi 32x128, Wse 32x128  = 96 KB
__global__ __launch_bounds__(256, 2) void k_layer(const float* __restrict__ Wi,
                                                  const float* __restrict__ bi,
                                                  const float* __restrict__ We,
                                                  const float* __restrict__ be,
                                                  const int* __restrict__ batch,
                                                  int parity, int last) {
    extern __shared__ float sm[];
    float2* Ai = (float2*)sm;            // [32][HD] duplicated pairs
    float2* Ae = Ai + 32 * HD;
    float* Wsi = (float*)(Ae + 32 * HD); // [32][HD]
    float* Wse = Wsi + 32 * HD;

    const float* hin = parity ? d_h2 : d_h;
    float* hout      = parity ? d_h  : d_h2;

    int t = threadIdx.x;
    int lane = t & 31, wid = t >> 5;
    int n0 = blockIdx.x * 32;

    // ---- gather phase: warp wid handles nodes wid*4 .. wid*4+3 ----
    for (int j = 0; j < 4; j++) {
        int nl = wid * 4 + j;
        int n = n0 + nl;
        // intra
        {
            int p = d_off_i[n], pe = d_off_i[n + 1];
            float4 a0 = {0, 0, 0, 0}, a1 = {0, 0, 0, 0};
            for (; p + 2 <= pe; p += 2) {
                int s0 = __ldg(d_csrc_i + p), s1 = __ldg(d_csrc_i + p + 1);
                float w0 = __ldg(d_cw_i + p), w1 = __ldg(d_cw_i + p + 1);
                float4 h0 = *(const float4*)(hin + (size_t)s0 * HD + lane * 4);
                float4 h1 = *(const float4*)(hin + (size_t)s1 * HD + lane * 4);
                a0.x += h0.x * w0; a0.y += h0.y * w0; a0.z += h0.z * w0; a0.w += h0.w * w0;
                a1.x += h1.x * w1; a1.y += h1.y * w1; a1.z += h1.z * w1; a1.w += h1.w * w1;
            }
            if (p < pe) {
                int s0 = __ldg(d_csrc_i + p);
                float w0 = __ldg(d_cw_i + p);
                float4 h0 = *(const float4*)(hin + (size_t)s0 * HD + lane * 4);
                a0.x += h0.x * w0; a0.y += h0.y * w0; a0.z += h0.z * w0; a0.w += h0.w * w0;
            }
            float4 v = make_float4(a0.x + a1.x, a0.y + a1.y, a0.z + a1.z, a0.w + a1.w);
            *(float4*)(Ai + nl * HD + lane * 4)     = make_float4(v.x, v.x, v.y, v.y);
            *(float4*)(Ai + nl * HD + lane * 4 + 2) = make_float4(v.z, v.z, v.w, v.w);
        }
        // inter
        {
            int p = d_off_e[n], pe = d_off_e[n + 1];
            float4 a0 = {0, 0, 0, 0}, a1 = {0, 0, 0, 0};
            for (; p + 2 <= pe; p += 2) {
                int s0 = __ldg(d_csrc_e + p), s1 = __ldg(d_csrc_e + p + 1);
                float w0 = __ldg(d_cw_e + p), w1 = __ldg(d_cw_e + p + 1);
                float4 h0 = *(const float4*)(hin + (size_t)s0 * HD + lane * 4);
                float4 h1 = *(const float4*)(hin + (size_t)s1 * HD + lane * 4);
                a0.x += h0.x * w0; a0.y += h0.y * w0; a0.z += h0.z * w0; a0.w += h0.w * w0;
                a1.x += h1.x * w1; a1.y += h1.y * w1; a1.z += h1.z * w1; a1.w += h1.w * w1;
            }
            if (p < pe) {
                int s0 = __ldg(d_csrc_e + p);
                float w0 = __ldg(d_cw_e + p);
                float4 h0 = *(const float4*)(hin + (size_t)s0 * HD + lane * 4);
                a0.x += h0.x * w0; a0.y += h0.y * w0; a0.z += h0.z * w0; a0.w += h0.w * w0;
            }
            float4 v = make_float4(a0.x + a1.x, a0.y + a1.y, a0.z + a1.z, a0.w + a1.w);
            *(float4*)(Ae + nl * HD + lane * 4)     = make_float4(v.x, v.x, v.y, v.y);
            *(float4*)(Ae + nl * HD + lane * 4 + 2) = make_float4(v.z, v.z, v.w, v.w);
        }
    }

    // ---- GEMM phase: thread = 2 rows x 8 cols, f32x2 packed ----
    int tx = t & 15, ty = t >> 4;
    unsigned long long acci[2][4], acce[2][4];
#pragma unroll
    for (int r = 0; r < 2; r++)
#pragma unroll
        for (int c = 0; c < 4; c++) { acci[r][c] = 0ull; acce[r][c] = 0ull; }

    const float2* Ar0i = Ai + (ty * 2 + 0) * HD;
    const float2* Ar1i = Ai + (ty * 2 + 1) * HD;
    const float2* Ar0e = Ae + (ty * 2 + 0) * HD;
    const float2* Ar1e = Ae + (ty * 2 + 1) * HD;

    for (int kc = 0; kc < HD; kc += 32) {
        __syncthreads();
#pragma unroll
        for (int i = 0; i < 4; i++) {
            int idx = t + i * 256;
            ((float4*)Wsi)[idx] = ((const float4*)(Wi + kc * HD))[idx];
            ((float4*)Wse)[idx] = ((const float4*)(We + kc * HD))[idx];
        }
        __syncthreads();
#pragma unroll
        for (int k = 0; k < 32; k++) {
            unsigned long long ai0 = *(const unsigned long long*)(Ar0i + kc + k);
            unsigned long long ai1 = *(const unsigned long long*)(Ar1i + kc + k);
            unsigned long long ae0 = *(const unsigned long long*)(Ar0e + kc + k);
            unsigned long long ae1 = *(const unsigned long long*)(Ar1e + kc + k);
            float4 wa = *(const float4*)(Wsi + k * HD + tx * 8);
            float4 wb = *(const float4*)(Wsi + k * HD + tx * 8 + 4);
            float4 va = *(const float4*)(Wse + k * HD + tx * 8);
            float4 vb = *(const float4*)(Wse + k * HD + tx * 8 + 4);
            unsigned long long w0 = pk(wa.x, wa.y), w1 = pk(wa.z, wa.w);
            unsigned long long w2 = pk(wb.x, wb.y), w3 = pk(wb.z, wb.w);
            unsigned long long u0 = pk(va.x, va.y), u1 = pk(va.z, va.w);
            unsigned long long u2 = pk(vb.x, vb.y), u3 = pk(vb.z, vb.w);
            fma2(acci[0][0], ai0, w0); fma2(acci[0][1], ai0, w1);
            fma2(acci[0][2], ai0, w2); fma2(acci[0][3], ai0, w3);
            fma2(acci[1][0], ai1, w0); fma2(acci[1][1], ai1, w1);
            fma2(acci[1][2], ai1, w2); fma2(acci[1][3], ai1, w3);
            fma2(acce[0][0], ae0, u0); fma2(acce[0][1], ae0, u1);
            fma2(acce[0][2], ae0, u2); fma2(acce[0][3], ae0, u3);
            fma2(acce[1][0], ae1, u0); fma2(acce[1][1], ae1, u1);
            fma2(acce[1][2], ae1, u2); fma2(acce[1][3], ae1, u3);
        }
    }

    // ---- epilogue ----
    int c0 = tx * 8;
    float bi8[8], be8[8];
    *(float4*)(bi8)     = *(const float4*)(bi + c0);
    *(float4*)(bi8 + 4) = *(const float4*)(bi + c0 + 4);
    *(float4*)(be8)     = *(const float4*)(be + c0);
    *(float4*)(be8 + 4) = *(const float4*)(be + c0 + 4);

#pragma unroll
    for (int r = 0; r < 2; r++) {
        int n = n0 + ty * 2 + r;
        float ci = d_cnti[n], inv = d_invi[n];
        float ce = d_cnte[n], lge = d_loge[n];
        float mi[8], me[8];
#pragma unroll
        for (int c = 0; c < 4; c++) {
            unpk(acci[r][c], mi[2 * c], mi[2 * c + 1]);
            unpk(acce[r][c], me[2 * c], me[2 * c + 1]);
        }
        float vp[8], vl[8], hh[8];
        *(float4*)(vp)     = *(const float4*)(d_vp + (size_t)n * HD + c0);
        *(float4*)(vp + 4) = *(const float4*)(d_vp + (size_t)n * HD + c0 + 4);
        *(float4*)(vl)     = *(const float4*)(d_vl + (size_t)n * HD + c0);
        *(float4*)(vl + 4) = *(const float4*)(d_vl + (size_t)n * HD + c0 + 4);
        *(float4*)(hh)     = *(const float4*)(hin + (size_t)n * HD + c0);
        *(float4*)(hh + 4) = *(const float4*)(hin + (size_t)n * HD + c0 + 4);
#pragma unroll
        for (int c = 0; c < 8; c++) {
            float m1 = (mi[c] + ci * bi8[c]) * inv;
            float m2 = (me[c] + ce * be8[c]) * lge;
            float nvp = siluf(m1 + vp[c]);
            float nvl = siluf(m2 + vl[c]);
            vp[c] = nvp;
            vl[c] = nvl;
            hh[c] += nvp + nvl;
        }
        *(float4*)(d_vp + (size_t)n * HD + c0)     = *(float4*)(vp);
        *(float4*)(d_vp + (size_t)n * HD + c0 + 4) = *(float4*)(vp + 4);
        *(float4*)(d_vl + (size_t)n * HD + c0)     = *(float4*)(vl);
        *(float4*)(d_vl + (size_t)n * HD + c0 + 4) = *(float4*)(vl + 4);
        *(float4*)(hout + (size_t)n * HD + c0)     = *(float4*)(hh);
        *(float4*)(hout + (size_t)n * HD + c0 + 4) = *(float4*)(hh + 4);
        if (last) {
            int bb = __ldg(batch + n);
            red_add_v4(d_pool + bb * HD + c0,     *(float4*)(hh));
            red_add_v4(d_pool + bb * HD + c0 + 4, *(float4*)(hh + 4));
        }
    }
}

// ---------------- FC head ----------------
__global__ __launch_bounds__(128) void k_fc(const float* __restrict__ W,
                                            const float* __restrict__ b,
                                            const float* __restrict__ gam,
                                            const float* __restrict__ bet,
                                            int swap) {
    __shared__ float gr[HD];
    int bid = blockIdx.x;
    int t = threadIdx.x;
    const float* gin = swap ? d_fcbuf : d_pool;
    float* gout = swap ? d_pool : d_fcbuf;
    gr[t] = gin[bid * HD + t];
    __syncthreads();
    float acc = b[t];
#pragma unroll 8
    for (int k = 0; k < HD; k++) acc += gr[k] * W[k * HD + t];
    acc = acc > 0.f ? acc : 0.01f * acc;
    float bnscale = rsqrtf(1.0f + 1e-5f);
    acc = acc * bnscale * gam[t] + bet[t];
    gout[bid * HD + t] = acc;
}

__global__ __launch_bounds__(128) void k_out(const float* __restrict__ oW,
                                             const float* __restrict__ ob,
                                             float* __restrict__ out) {
    __shared__ float part[4];
    int b = blockIdx.x;
    int t = threadIdx.x;
    float p = d_fcbuf[b * HD + t] * oW[t];
#pragma unroll
    for (int o = 16; o > 0; o >>= 1) p += __shfl_down_sync(0xffffffffu, p, o);
    if ((t & 31) == 0) part[t >> 5] = p;
    __syncthreads();
    if (t == 0) out[b] = part[0] + part[1] + part[2] + part[3] + ob[0];
}

// ---------------- host launcher ----------------
extern "C" void kernel_launch(void* const* d_in, const int* in_sizes, int n_in,
                              void* d_out, int out_size) {
    const float* x     = (const float*)d_in[0];
    const int*   ei    = (const int*)d_in[1];
    const int*   ee    = (const int*)d_in[2];
    const float* pos   = (const float*)d_in[3];
    const float* eattr = (const float*)d_in[4];
    const int*   batch = (const int*)d_in[5];
    const float* lnW   = (const float*)d_in[6];
    const float* lnb   = (const float*)d_in[7];
    const float* Wi    = (const float*)d_in[8];
    const float* bi    = (const float*)d_in[9];
    const float* We    = (const float*)d_in[10];
    const float* be    = (const float*)d_in[11];
    const float* fcW   = (const float*)d_in[12];
    const float* fcb   = (const float*)d_in[13];
    const float* gam   = (const float*)d_in[14];
    const float* bet   = (const float*)d_in[15];
    const float* oW    = (const float*)d_in[16];
    const float* ob    = (const float*)d_in[17];
    float* out = (float*)d_out;

    static int smem_set = 0;
    if (!smem_set) {
        cudaFuncSetAttribute(k_layer, cudaFuncAttributeMaxDynamicSharedMemorySize, 98304);
        smem_set = 1;
    }

    k_zero_pre<<<(NN + 255) / 256, 256>>>();
    k_linnode<<<NN / 8, 128>>>(x, lnW, lnb);
    k_deg_intra<<<(EI + 255) / 256, 256>>>(ei);
    k_deg_inter<<<(EE + 255) / 256, 256>>>(ee, pos);

    k_scan_a<<<NBLK_SCAN, 1024>>>(0);
    k_scan_a<<<NBLK_SCAN, 1024>>>(1);
    k_scan_b<<<1, 32>>>();
    k_scan_c<<<NBLK_SCAN, 1024>>>(0);
    k_scan_c<<<NBLK_SCAN, 1024>>>(1);
    k_factors<<<(NN + 255) / 256, 256>>>();
    k_fill_i<<<(EI + 255) / 256, 256>>>(ei, eattr);
    k_fill_e<<<(EE + 255) / 256, 256>>>(ee);

    for (int l = 0; l < 4; l++) {
        k_layer<<<NN / 32, 256, 98304>>>(Wi + l * HD * HD, bi + l * HD,
                                         We + l * HD * HD, be + l * HD,
                                         batch, l & 1, l == 3);
    }

    k_fc<<<GB, 128>>>(fcW + 0 * HD * HD, fcb + 0 * HD, gam + 0 * HD, bet + 0 * HD, 0);
    k_fc<<<GB, 128>>>(fcW + 1 * HD * HD, fcb + 1 * HD, gam + 1 * HD, bet + 1 * HD, 1);
    k_fc<<<GB, 128>>>(fcW + 2 * HD * HD, fcb + 2 * HD, gam + 2 * HD, bet + 2 * HD, 0);
    k_out<<<GB, 128>>>(oW, ob, out);
}

// round 4
// speedup vs baseline: 1.6268x; 1.6268x over previous
#include <cuda_runtime.h>
#include <math.h>

#define NN 100000
#define NP 100032          // padded to 64-row tiles (1563*64)
#define EI 800000
#define EE 400000
#define HD 128
#define GB 256
#define ND 35
#define NBLK_SCAN 98       // ceil(100000/1024)

typedef unsigned long long ull;

// ---------------- device scratch ----------------
__device__ float d_h [NN * HD];
__device__ float d_h2[NN * HD];
__device__ float d_vp[NN * HD];
__device__ float d_vl[NN * HD];
__device__ float d_aggi[NP * HD];
__device__ float d_agge[NP * HD];
__device__ float d_wint[EE];
__device__ int   d_ecnt_i[NN];
__device__ int   d_ecnt_e[NN];
__device__ int   d_fill_i[NN];
__device__ int   d_fill_e[NN];
__device__ int   d_off_i[NN + 1];
__device__ int   d_off_e[NN + 1];
__device__ int   d_bsum_i[NBLK_SCAN];
__device__ int   d_bsum_e[NBLK_SCAN];
__device__ int   d_csrc_i[EI];
__device__ float d_cw_i[EI];
__device__ int   d_csrc_e[EE];
__device__ float d_cw_e[EE];
__device__ float d_cnti[NN];
__device__ float d_cnte[NN];
__device__ float d_invi[NN];
__device__ float d_loge[NN];
__device__ float d_pool[GB * HD];
__device__ float d_fcbuf[GB * HD];

// ---------------- helpers ----------------
__device__ __forceinline__ float siluf(float v) { return v / (1.0f + expf(-v)); }

__device__ __forceinline__ void red_add_v4(float* p, float4 v) {
    asm volatile("red.global.add.v4.f32 [%0], {%1,%2,%3,%4};"
                 :: "l"(p), "f"(v.x), "f"(v.y), "f"(v.z), "f"(v.w) : "memory");
}

__device__ __forceinline__ ull pk(float x, float y) {
    ull r;
    asm("mov.b64 %0, {%1, %2};" : "=l"(r) : "f"(x), "f"(y));
    return r;
}
__device__ __forceinline__ void unpk(ull v, float& lo, float& hi) {
    asm("mov.b64 {%0, %1}, %2;" : "=f"(lo), "=f"(hi) : "l"(v));
}
__device__ __forceinline__ void fma2(ull& d, ull a, ull b) {
    asm("fma.rn.f32x2 %0, %1, %2, %0;" : "+l"(d) : "l"(a), "l"(b));
}

// ---------------- init ----------------
__global__ void k_zero_pre() {
    int i = blockIdx.x * blockDim.x + threadIdx.x;
    if (i < NN) {
        d_ecnt_i[i] = 0; d_ecnt_e[i] = 0;
        d_fill_i[i] = 0; d_fill_e[i] = 0;
    }
    if (i < GB * HD) d_pool[i] = 0.0f;
}

// lin_node: h = silu(x @ W + b); vp = vl = 0
__global__ __launch_bounds__(128) void k_linnode(const float* __restrict__ x,
                                                 const float* __restrict__ W,
                                                 const float* __restrict__ b) {
    __shared__ float Ws[ND * HD];
    __shared__ float xs[8][ND];
    int t = threadIdx.x;
    for (int i = t; i < ND * HD; i += 128) Ws[i] = W[i];
    int n0 = blockIdx.x * 8;
    for (int i = t; i < 8 * ND; i += 128) {
        int nn = i / ND, k = i % ND;
        xs[nn][k] = x[(n0 + nn) * ND + k];
    }
    __syncthreads();
    float bb = b[t];
    for (int nn = 0; nn < 8; nn++) {
        int n = n0 + nn;
        float acc = bb;
#pragma unroll
        for (int k = 0; k < ND; k++) acc += xs[nn][k] * Ws[k * HD + t];
        d_h[n * HD + t] = siluf(acc);
        d_vp[n * HD + t] = 0.0f;
        d_vl[n * HD + t] = 0.0f;
    }
}

// ---------------- degree counting + geometric weights ----------------
__global__ void k_deg_intra(const int* __restrict__ ei) {
    int e = blockIdx.x * blockDim.x + threadIdx.x;
    if (e < EI) atomicAdd(&d_ecnt_i[ei[EI + e]], 1);
}

__global__ void k_deg_inter(const int* __restrict__ ee, const float* __restrict__ pos) {
    int e = blockIdx.x * blockDim.x + threadIdx.x;
    if (e < EE) {
        int s = ee[e], d = ee[EE + e];
        float dx = pos[s * 3 + 0] - pos[d * 3 + 0];
        float dy = pos[s * 3 + 1] - pos[d * 3 + 1];
        float dz = pos[s * 3 + 2] - pos[d * 3 + 2];
        d_wint[e] = expf(-(dx * dx + dy * dy + dz * dz));
        atomicAdd(&d_ecnt_e[d], 1);
    }
}

// ---------------- prefix scan (exclusive) -> CSR offsets ----------------
__global__ __launch_bounds__(1024) void k_scan_a(int which) {
    __shared__ int sh[1024];
    const int* cnt = which ? d_ecnt_e : d_ecnt_i;
    int* off = which ? d_off_e : d_off_i;
    int* bs  = which ? d_bsum_e : d_bsum_i;
    int tid = threadIdx.x;
    int i = blockIdx.x * 1024 + tid;
    int v = (i < NN) ? cnt[i] : 0;
    sh[tid] = v;
    __syncthreads();
#pragma unroll
    for (int o = 1; o < 1024; o <<= 1) {
        int u = (tid >= o) ? sh[tid - o] : 0;
        __syncthreads();
        sh[tid] += u;
        __syncthreads();
    }
    if (i <= NN) off[i] = sh[tid] - v;  // exclusive
    if (tid == 1023) bs[blockIdx.x] = sh[1023];
}

__global__ void k_scan_b() {
    if (threadIdx.x == 0) {
        int r = 0;
        for (int b = 0; b < NBLK_SCAN; b++) { int t = d_bsum_i[b]; d_bsum_i[b] = r; r += t; }
    }
    if (threadIdx.x == 1) {
        int r = 0;
        for (int b = 0; b < NBLK_SCAN; b++) { int t = d_bsum_e[b]; d_bsum_e[b] = r; r += t; }
    }
}

__global__ __launch_bounds__(1024) void k_scan_c(int which) {
    int* off = which ? d_off_e : d_off_i;
    const int* bs = which ? d_bsum_e : d_bsum_i;
    int i = blockIdx.x * 1024 + threadIdx.x;
    if (i <= NN) off[i] += bs[blockIdx.x];
}

__global__ void k_factors() {
    int n = blockIdx.x * blockDim.x + threadIdx.x;
    if (n < NN) {
        float ci = (float)d_ecnt_i[n];
        float ce = (float)d_ecnt_e[n];
        d_cnti[n] = ci;
        d_cnte[n] = ce;
        d_invi[n] = 1.0f / (ci + 1.0f);
        d_loge[n] = logf(ce + 1.0f);
    }
}

// ---------------- CSR fill ----------------
__global__ void k_fill_i(const int* __restrict__ ei, const float* __restrict__ ea) {
    int e = blockIdx.x * blockDim.x + threadIdx.x;
    if (e < EI) {
        int s = ei[e], d = ei[EI + e];
        int p = d_off_i[d] + atomicAdd(&d_fill_i[d], 1);
        d_csrc_i[p] = s;
        d_cw_i[p] = ea[e];
    }
}

__global__ void k_fill_e(const int* __restrict__ ee) {
    int e = blockIdx.x * blockDim.x + threadIdx.x;
    if (e < EE) {
        int s = ee[e], d = ee[EE + e];
        int p = d_off_e[d] + atomicAdd(&d_fill_e[d], 1);
        d_csrc_e[p] = s;
        d_cw_e[p] = d_wint[e];
    }
}

// ---------------- CSR gather: warp per node, both edge types ----------------
__global__ __launch_bounds__(256) void k_gather(int parity) {
    int g = blockIdx.x * 256 + threadIdx.x;
    int n = g >> 5;
    int lane = g & 31;
    if (n >= NN) return;
    const float* __restrict__ hin = parity ? d_h2 : d_h;

    // intra
    {
        int p = d_off_i[n], pe = d_off_i[n + 1];
        float4 a0 = {0, 0, 0, 0}, a1 = {0, 0, 0, 0};
        for (; p + 4 <= pe; p += 4) {
            int s0 = __ldg(d_csrc_i + p);
            int s1 = __ldg(d_csrc_i + p + 1);
            int s2 = __ldg(d_csrc_i + p + 2);
            int s3 = __ldg(d_csrc_i + p + 3);
            float w0 = __ldg(d_cw_i + p);
            float w1 = __ldg(d_cw_i + p + 1);
            float w2 = __ldg(d_cw_i + p + 2);
            float w3 = __ldg(d_cw_i + p + 3);
            float4 h0 = *(const float4*)(hin + (size_t)s0 * HD + lane * 4);
            float4 h1 = *(const float4*)(hin + (size_t)s1 * HD + lane * 4);
            float4 h2 = *(const float4*)(hin + (size_t)s2 * HD + lane * 4);
            float4 h3 = *(const float4*)(hin + (size_t)s3 * HD + lane * 4);
            a0.x += h0.x * w0; a0.y += h0.y * w0; a0.z += h0.z * w0; a0.w += h0.w * w0;
            a1.x += h1.x * w1; a1.y += h1.y * w1; a1.z += h1.z * w1; a1.w += h1.w * w1;
            a0.x += h2.x * w2; a0.y += h2.y * w2; a0.z += h2.z * w2; a0.w += h2.w * w2;
            a1.x += h3.x * w3; a1.y += h3.y * w3; a1.z += h3.z * w3; a1.w += h3.w * w3;
        }
        for (; p < pe; p++) {
            int s0 = __ldg(d_csrc_i + p);
            float w0 = __ldg(d_cw_i + p);
            float4 h0 = *(const float4*)(hin + (size_t)s0 * HD + lane * 4);
            a0.x += h0.x * w0; a0.y += h0.y * w0; a0.z += h0.z * w0; a0.w += h0.w * w0;
        }
        *(float4*)(d_aggi + (size_t)n * HD + lane * 4) =
            make_float4(a0.x + a1.x, a0.y + a1.y, a0.z + a1.z, a0.w + a1.w);
    }
    // inter
    {
        int p = d_off_e[n], pe = d_off_e[n + 1];
        float4 a0 = {0, 0, 0, 0}, a1 = {0, 0, 0, 0};
        for (; p + 4 <= pe; p += 4) {
            int s0 = __ldg(d_csrc_e + p);
            int s1 = __ldg(d_csrc_e + p + 1);
            int s2 = __ldg(d_csrc_e + p + 2);
            int s3 = __ldg(d_csrc_e + p + 3);
            float w0 = __ldg(d_cw_e + p);
            float w1 = __ldg(d_cw_e + p + 1);
            float w2 = __ldg(d_cw_e + p + 2);
            float w3 = __ldg(d_cw_e + p + 3);
            float4 h0 = *(const float4*)(hin + (size_t)s0 * HD + lane * 4);
            float4 h1 = *(const float4*)(hin + (size_t)s1 * HD + lane * 4);
            float4 h2 = *(const float4*)(hin + (size_t)s2 * HD + lane * 4);
            float4 h3 = *(const float4*)(hin + (size_t)s3 * HD + lane * 4);
            a0.x += h0.x * w0; a0.y += h0.y * w0; a0.z += h0.z * w0; a0.w += h0.w * w0;
            a1.x += h1.x * w1; a1.y += h1.y * w1; a1.z += h1.z * w1; a1.w += h1.w * w1;
            a0.x += h2.x * w2; a0.y += h2.y * w2; a0.z += h2.z * w2; a0.w += h2.w * w2;
            a1.x += h3.x * w3; a1.y += h3.y * w3; a1.z += h3.z * w3; a1.w += h3.w * w3;
        }
        for (; p < pe; p++) {
            int s0 = __ldg(d_csrc_e + p);
            float w0 = __ldg(d_cw_e + p);
            float4 h0 = *(const float4*)(hin + (size_t)s0 * HD + lane * 4);
            a0.x += h0.x * w0; a0.y += h0.y * w0; a0.z += h0.z * w0; a0.w += h0.w * w0;
        }
        *(float4*)(d_agge + (size_t)n * HD + lane * 4) =
            make_float4(a0.x + a1.x, a0.y + a1.y, a0.z + a1.z, a0.w + a1.w);
    }
}

// ---------------- dual GEMM (f32x2) + SiLU state update ----------------
// 64-row tile, 256 threads, 4 rows x 8 cols x 2 gemms per thread.
// smem: A (2 x 64x128 f32 = 64KB) + W chunk (2 x 32x128 f32 = 32KB) = 96KB
__global__ __launch_bounds__(256, 2) void k_update2(const float* __restrict__ Wi,
                                                    const float* __restrict__ bi,
                                                    const float* __restrict__ We,
                                                    const float* __restrict__ be,
                                                    const int* __restrict__ batch,
                                                    int parity, int last) {
    extern __shared__ float sm[];
    float* Asi = sm;                 // [64][128]
    float* Ase = Asi + 64 * HD;      // [64][128]
    float* Wsi = Ase + 64 * HD;      // [32][128]
    float* Wse = Wsi + 32 * HD;      // [32][128]

    const float* __restrict__ hin = parity ? d_h2 : d_h;
    float* hout = parity ? d_h : d_h2;

    int t = threadIdx.x;
    int tx = t & 15, ty = t >> 4;
    int n0 = blockIdx.x * 64;

    // stage A tiles (padded arrays: reads up to NP safe)
    {
        const float4* ga = (const float4*)(d_aggi + (size_t)n0 * HD);
        const float4* ge = (const float4*)(d_agge + (size_t)n0 * HD);
#pragma unroll
        for (int i = 0; i < 8; i++) {
            int idx = t + i * 256;
            ((float4*)Asi)[idx] = ga[idx];
            ((float4*)Ase)[idx] = ge[idx];
        }
    }

    ull acci[4][4], acce[4][4];
#pragma unroll
    for (int r = 0; r < 4; r++)
#pragma unroll
        for (int c = 0; c < 4; c++) { acci[r][c] = 0ull; acce[r][c] = 0ull; }

    for (int kc = 0; kc < HD; kc += 32) {
        __syncthreads();
#pragma unroll
        for (int i = 0; i < 4; i++) {
            int idx = t + i * 256;
            ((float4*)Wsi)[idx] = ((const float4*)(Wi + kc * HD))[idx];
            ((float4*)Wse)[idx] = ((const float4*)(We + kc * HD))[idx];
        }
        __syncthreads();
#pragma unroll
        for (int k = 0; k < 32; k++) {
            ull ai[4], ae[4];
#pragma unroll
            for (int r = 0; r < 4; r++) {
                float a = Asi[(ty * 4 + r) * HD + kc + k];
                float e = Ase[(ty * 4 + r) * HD + kc + k];
                ai[r] = pk(a, a);
                ae[r] = pk(e, e);
            }
            float4 wa = *(const float4*)(Wsi + k * HD + tx * 8);
            float4 wb = *(const float4*)(Wsi + k * HD + tx * 8 + 4);
            float4 va = *(const float4*)(Wse + k * HD + tx * 8);
            float4 vb = *(const float4*)(Wse + k * HD + tx * 8 + 4);
            ull w0 = pk(wa.x, wa.y), w1 = pk(wa.z, wa.w);
            ull w2 = pk(wb.x, wb.y), w3 = pk(wb.z, wb.w);
            ull u0 = pk(va.x, va.y), u1 = pk(va.z, va.w);
            ull u2 = pk(vb.x, vb.y), u3 = pk(vb.z, vb.w);
#pragma unroll
            for (int r = 0; r < 4; r++) {
                fma2(acci[r][0], ai[r], w0); fma2(acci[r][1], ai[r], w1);
                fma2(acci[r][2], ai[r], w2); fma2(acci[r][3], ai[r], w3);
                fma2(acce[r][0], ae[r], u0); fma2(acce[r][1], ae[r], u1);
                fma2(acce[r][2], ae[r], u2); fma2(acce[r][3], ae[r], u3);
            }
        }
    }

    // epilogue
    int c0 = tx * 8;
    float bi8[8], be8[8];
    *(float4*)(bi8)     = *(const float4*)(bi + c0);
    *(float4*)(bi8 + 4) = *(const float4*)(bi + c0 + 4);
    *(float4*)(be8)     = *(const float4*)(be + c0);
    *(float4*)(be8 + 4) = *(const float4*)(be + c0 + 4);

#pragma unroll
    for (int r = 0; r < 4; r++) {
        int n = n0 + ty * 4 + r;
        if (n >= NN) continue;
        float ci = d_cnti[n], inv = d_invi[n];
        float ce = d_cnte[n], lge = d_loge[n];
        float mi[8], me[8];
#pragma unroll
        for (int c = 0; c < 4; c++) {
            unpk(acci[r][c], mi[2 * c], mi[2 * c + 1]);
            unpk(acce[r][c], me[2 * c], me[2 * c + 1]);
        }
        float vp[8], vl[8], hh[8];
        *(float4*)(vp)     = *(const float4*)(d_vp + (size_t)n * HD + c0);
        *(float4*)(vp + 4) = *(const float4*)(d_vp + (size_t)n * HD + c0 + 4);
        *(float4*)(vl)     = *(const float4*)(d_vl + (size_t)n * HD + c0);
        *(float4*)(vl + 4) = *(const float4*)(d_vl + (size_t)n * HD + c0 + 4);
        *(float4*)(hh)     = *(const float4*)(hin + (size_t)n * HD + c0);
        *(float4*)(hh + 4) = *(const float4*)(hin + (size_t)n * HD + c0 + 4);
#pragma unroll
        for (int c = 0; c < 8; c++) {
            float m1 = (mi[c] + ci * bi8[c]) * inv;
            float m2 = (me[c] + ce * be8[c]) * lge;
            float nvp = siluf(m1 + vp[c]);
            float nvl = siluf(m2 + vl[c]);
            vp[c] = nvp;
            vl[c] = nvl;
            hh[c] += nvp + nvl;
        }
        *(float4*)(d_vp + (size_t)n * HD + c0)     = *(float4*)(vp);
        *(float4*)(d_vp + (size_t)n * HD + c0 + 4) = *(float4*)(vp + 4);
        *(float4*)(d_vl + (size_t)n * HD + c0)     = *(float4*)(vl);
        *(float4*)(d_vl + (size_t)n * HD + c0 + 4) = *(float4*)(vl + 4);
        *(float4*)(hout + (size_t)n * HD + c0)     = *(float4*)(hh);
        *(float4*)(hout + (size_t)n * HD + c0 + 4) = *(float4*)(hh + 4);
        if (last) {
            int bb = __ldg(batch + n);
            red_add_v4(d_pool + bb * HD + c0,     *(float4*)(hh));
            red_add_v4(d_pool + bb * HD + c0 + 4, *(float4*)(hh + 4));
        }
    }
}

// ---------------- FC head ----------------
__global__ __launch_bounds__(128) void k_fc(const float* __restrict__ W,
                                            const float* __restrict__ b,
                                            const float* __restrict__ gam,
                                            const float* __restrict__ bet,
                                            int swap) {
    __shared__ float gr[HD];
    int bid = blockIdx.x;
    int t = threadIdx.x;
    const float* gin = swap ? d_fcbuf : d_pool;
    float* gout = swap ? d_pool : d_fcbuf;
    gr[t] = gin[bid * HD + t];
    __syncthreads();
    float acc = b[t];
#pragma unroll 8
    for (int k = 0; k < HD; k++) acc += gr[k] * W[k * HD + t];
    acc = acc > 0.f ? acc : 0.01f * acc;
    float bnscale = rsqrtf(1.0f + 1e-5f);
    acc = acc * bnscale * gam[t] + bet[t];
    gout[bid * HD + t] = acc;
}

__global__ __launch_bounds__(128) void k_out(const float* __restrict__ oW,
                                             const float* __restrict__ ob,
                                             float* __restrict__ out) {
    __shared__ float part[4];
    int b = blockIdx.x;
    int t = threadIdx.x;
    float p = d_fcbuf[b * HD + t] * oW[t];
#pragma unroll
    for (int o = 16; o > 0; o >>= 1) p += __shfl_down_sync(0xffffffffu, p, o);
    if ((t & 31) == 0) part[t >> 5] = p;
    __syncthreads();
    if (t == 0) out[b] = part[0] + part[1] + part[2] + part[3] + ob[0];
}

// ---------------- host launcher ----------------
extern "C" void kernel_launch(void* const* d_in, const int* in_sizes, int n_in,
                              void* d_out, int out_size) {
    const float* x     = (const float*)d_in[0];
    const int*   ei    = (const int*)d_in[1];
    const int*   ee    = (const int*)d_in[2];
    const float* pos   = (const float*)d_in[3];
    const float* eattr = (const float*)d_in[4];
    const int*   batch = (const int*)d_in[5];
    const float* lnW   = (const float*)d_in[6];
    const float* lnb   = (const float*)d_in[7];
    const float* Wi    = (const float*)d_in[8];
    const float* bi    = (const float*)d_in[9];
    const float* We    = (const float*)d_in[10];
    const float* be    = (const float*)d_in[11];
    const float* fcW   = (const float*)d_in[12];
    const float* fcb   = (const float*)d_in[13];
    const float* gam   = (const float*)d_in[14];
    const float* bet   = (const float*)d_in[15];
    const float* oW    = (const float*)d_in[16];
    const float* ob    = (const float*)d_in[17];
    float* out = (float*)d_out;

    static int smem_set = 0;
    if (!smem_set) {
        cudaFuncSetAttribute(k_update2, cudaFuncAttributeMaxDynamicSharedMemorySize, 98304);
        smem_set = 1;
    }

    k_zero_pre<<<(NN + 255) / 256, 256>>>();
    k_linnode<<<NN / 8, 128>>>(x, lnW, lnb);
    k_deg_intra<<<(EI + 255) / 256, 256>>>(ei);
    k_deg_inter<<<(EE + 255) / 256, 256>>>(ee, pos);

    k_scan_a<<<NBLK_SCAN, 1024>>>(0);
    k_scan_a<<<NBLK_SCAN, 1024>>>(1);
    k_scan_b<<<1, 32>>>();
    k_scan_c<<<NBLK_SCAN, 1024>>>(0);
    k_scan_c<<<NBLK_SCAN, 1024>>>(1);
    k_factors<<<(NN + 255) / 256, 256>>>();
    k_fill_i<<<(EI + 255) / 256, 256>>>(ei, eattr);
    k_fill_e<<<(EE + 255) / 256, 256>>>(ee);

    for (int l = 0; l < 4; l++) {
        k_gather<<<(NN * 32 + 255) / 256, 256>>>(l & 1);
        k_update2<<<(NN + 63) / 64, 256, 98304>>>(Wi + l * HD * HD, bi + l * HD,
                                                  We + l * HD * HD, be + l * HD,
                                                  batch, l & 1, l == 3);
    }

    k_fc<<<GB, 128>>>(fcW + 0 * HD * HD, fcb + 0 * HD, gam + 0 * HD, bet + 0 * HD, 0);
    k_fc<<<GB, 128>>>(fcW + 1 * HD * HD, fcb + 1 * HD, gam + 1 * HD, bet + 1 * HD, 1);
    k_fc<<<GB, 128>>>(fcW + 2 * HD * HD, fcb + 2 * HD, gam + 2 * HD, bet + 2 * HD, 0);
    k_out<<<GB, 128>>>(oW, ob, out);
}

// round 9
// speedup vs baseline: 2.3003x; 1.4140x over previous
#include <cuda_runtime.h>
#include <cuda_bf16.h>
#include <math.h>

#define NN 100000
#define NP 100096          // padded ( >= 1563*64 = 100032 )
#define NBLK_UPD 1563
#define EI 800000
#define EE 400000
#define HD 128
#define GB 256
#define ND 35
#define NBLK_SCAN 98       // ceil(100000/1024)

typedef unsigned long long ull;

// ---------------- device scratch ----------------
__device__ float d_h [NN * HD];
__device__ float d_h2[NN * HD];
__device__ float d_vp[NN * HD];
__device__ float d_vl[NN * HD];
__device__ float d_aggi[NP * HD];
__device__ float d_agge[NP * HD];
__device__ float d_wint[EE];
__device__ int   d_ecnt_i[NN];
__device__ int   d_ecnt_e[NN];
__device__ int   d_fill_i[NN];
__device__ int   d_fill_e[NN];
__device__ int   d_off_i[NN + 1];
__device__ int   d_off_e[NN + 1];
__device__ int   d_bsum_i[NBLK_SCAN];
__device__ int   d_bsum_e[NBLK_SCAN];
__device__ int   d_csrc_i[EI];
__device__ float d_cw_i[EI];
__device__ int   d_csrc_e[EE];
__device__ float d_cw_e[EE];
__device__ float d_cnti[NN];
__device__ float d_cnte[NN];
__device__ float d_invi[NN];
__device__ float d_loge[NN];
__device__ float d_pool[GB * HD];
__device__ float d_fcbuf[GB * HD];
// weight image: bf16 hi/lo split, transposed [n][k] pairs packed in 32-bit words.
// piece index pb = layer*4 + mat*2 + (0=hi,1=lo); each piece = 128 n-rows x 64 k-words.
__device__ unsigned d_wimg[4 * 2 * 2 * 128 * 64];

// ---------------- helpers ----------------
__device__ __forceinline__ float siluf(float v) { return v / (1.0f + expf(-v)); }

// d = {hi=bf16(a1), lo=bf16(a0)}
__device__ __forceinline__ unsigned bf16x2_of(float a0, float a1) {
    unsigned w;
    asm("cvt.rn.bf16x2.f32 %0, %1, %2;" : "=r"(w) : "f"(a1), "f"(a0));
    return w;
}

__device__ __forceinline__ void mma16816(float* d, const unsigned* a, const unsigned* b) {
    asm volatile("mma.sync.aligned.m16n8k16.row.col.f32.bf16.bf16.f32 "
                 "{%0,%1,%2,%3}, {%4,%5,%6,%7}, {%8,%9}, {%0,%1,%2,%3};"
                 : "+f"(d[0]), "+f"(d[1]), "+f"(d[2]), "+f"(d[3])
                 : "r"(a[0]), "r"(a[1]), "r"(a[2]), "r"(a[3]), "r"(b[0]), "r"(b[1]));
}

// ---------------- init ----------------
__global__ void k_zero_pre() {
    int i = blockIdx.x * blockDim.x + threadIdx.x;
    if (i < NN) {
        d_ecnt_i[i] = 0; d_ecnt_e[i] = 0;
        d_fill_i[i] = 0; d_fill_e[i] = 0;
    }
    if (i < GB * HD) d_pool[i] = 0.0f;
}

// lin_node: h = silu(x @ W + b); vp = vl = 0
__global__ __launch_bounds__(128) void k_linnode(const float* __restrict__ x,
                                                 const float* __restrict__ W,
                                                 const float* __restrict__ b) {
    __shared__ float Ws[ND * HD];
    __shared__ float xs[8][ND];
    int t = threadIdx.x;
    for (int i = t; i < ND * HD; i += 128) Ws[i] = W[i];
    int n0 = blockIdx.x * 8;
    for (int i = t; i < 8 * ND; i += 128) {
        int nn = i / ND, k = i % ND;
        xs[nn][k] = x[(n0 + nn) * ND + k];
    }
    __syncthreads();
    float bb = b[t];
    for (int nn = 0; nn < 8; nn++) {
        int n = n0 + nn;
        float acc = bb;
#pragma unroll
        for (int k = 0; k < ND; k++) acc += xs[nn][k] * Ws[k * HD + t];
        d_h[n * HD + t] = siluf(acc);
        d_vp[n * HD + t] = 0.0f;
        d_vl[n * HD + t] = 0.0f;
    }
}

// ---------------- degree counting + geometric weights ----------------
__global__ void k_deg_intra(const int* __restrict__ ei) {
    int e = blockIdx.x * blockDim.x + threadIdx.x;
    if (e < EI) atomicAdd(&d_ecnt_i[ei[EI + e]], 1);
}

__global__ void k_deg_inter(const int* __restrict__ ee, const float* __restrict__ pos) {
    int e = blockIdx.x * blockDim.x + threadIdx.x;
    if (e < EE) {
        int s = ee[e], d = ee[EE + e];
        float dx = pos[s * 3 + 0] - pos[d * 3 + 0];
        float dy = pos[s * 3 + 1] - pos[d * 3 + 1];
        float dz = pos[s * 3 + 2] - pos[d * 3 + 2];
        d_wint[e] = expf(-(dx * dx + dy * dy + dz * dz));
        atomicAdd(&d_ecnt_e[d], 1);
    }
}

// ---------------- prefix scan (exclusive) -> CSR offsets ----------------
__global__ __launch_bounds__(1024) void k_scan_a(int which) {
    __shared__ int sh[1024];
    const int* cnt = which ? d_ecnt_e : d_ecnt_i;
    int* off = which ? d_off_e : d_off_i;
    int* bs  = which ? d_bsum_e : d_bsum_i;
    int tid = threadIdx.x;
    int i = blockIdx.x * 1024 + tid;
    int v = (i < NN) ? cnt[i] : 0;
    sh[tid] = v;
    __syncthreads();
#pragma unroll
    for (int o = 1; o < 1024; o <<= 1) {
        int u = (tid >= o) ? sh[tid - o] : 0;
        __syncthreads();
        sh[tid] += u;
        __syncthreads();
    }
    if (i <= NN) off[i] = sh[tid] - v;  // exclusive
    if (tid == 1023) bs[blockIdx.x] = sh[1023];
}

__global__ void k_scan_b() {
    if (threadIdx.x == 0) {
        int r = 0;
        for (int b = 0; b < NBLK_SCAN; b++) { int t = d_bsum_i[b]; d_bsum_i[b] = r; r += t; }
    }
    if (threadIdx.x == 1) {
        int r = 0;
        for (int b = 0; b < NBLK_SCAN; b++) { int t = d_bsum_e[b]; d_bsum_e[b] = r; r += t; }
    }
}

__global__ __launch_bounds__(1024) void k_scan_c(int which) {
    int* off = which ? d_off_e : d_off_i;
    const int* bs = which ? d_bsum_e : d_bsum_i;
    int i = blockIdx.x * 1024 + threadIdx.x;
    if (i <= NN) off[i] += bs[blockIdx.x];
}

__global__ void k_factors() {
    int n = blockIdx.x * blockDim.x + threadIdx.x;
    if (n < NN) {
        float ci = (float)d_ecnt_i[n];
        float ce = (float)d_ecnt_e[n];
        d_cnti[n] = ci;
        d_cnte[n] = ce;
        d_invi[n] = 1.0f / (ci + 1.0f);
        d_loge[n] = logf(ce + 1.0f);
    }
}

// ---------------- CSR fill ----------------
__global__ void k_fill_i(const int* __restrict__ ei, const float* __restrict__ ea) {
    int e = blockIdx.x * blockDim.x + threadIdx.x;
    if (e < EI) {
        int s = ei[e], d = ei[EI + e];
        int p = d_off_i[d] + atomicAdd(&d_fill_i[d], 1);
        d_csrc_i[p] = s;
        d_cw_i[p] = ea[e];
    }
}

__global__ void k_fill_e(const int* __restrict__ ee) {
    int e = blockIdx.x * blockDim.x + threadIdx.x;
    if (e < EE) {
        int s = ee[e], d = ee[EE + e];
        int p = d_off_e[d] + atomicAdd(&d_fill_e[d], 1);
        d_csrc_e[p] = s;
        d_cw_e[p] = d_wint[e];
    }
}

// ---------------- weight prep: transpose + bf16 hi/lo split (once) ----------------
__global__ void k_prepw(const float* __restrict__ Wi, const float* __restrict__ We) {
    int gid = blockIdx.x * blockDim.x + threadIdx.x;
    if (gid >= 65536) return;
    int j = gid & 63;            // k-pair word
    int n = (gid >> 6) & 127;    // output col = B n-row
    int m = (gid >> 13) & 1;
    int l = gid >> 14;
    const float* Wsrc = (m ? We : Wi) + l * HD * HD;
    int k0 = 2 * j;
    float w0 = Wsrc[k0 * HD + n];
    float w1 = Wsrc[(k0 + 1) * HD + n];
    unsigned wh = bf16x2_of(w0, w1);
    float r0 = w0 - __uint_as_float(wh << 16);
    float r1 = w1 - __uint_as_float(wh & 0xffff0000u);
    unsigned wl = bf16x2_of(r0, r1);
    int pb = l * 4 + m * 2;
    d_wimg[(size_t)pb * 8192 + n * 64 + j] = wh;
    d_wimg[(size_t)(pb + 1) * 8192 + n * 64 + j] = wl;
}

// ---------------- CSR gather: warp per node, both edge types ----------------
__global__ __launch_bounds__(256) void k_gather(int parity) {
    int g = blockIdx.x * 256 + threadIdx.x;
    int n = g >> 5;
    int lane = g & 31;
    if (n >= NN) return;
    const float* __restrict__ hin = parity ? d_h2 : d_h;

    // intra
    {
        int p = d_off_i[n], pe = d_off_i[n + 1];
        float4 a0 = {0, 0, 0, 0}, a1 = {0, 0, 0, 0};
        for (; p + 4 <= pe; p += 4) {
            int s0 = __ldg(d_csrc_i + p);
            int s1 = __ldg(d_csrc_i + p + 1);
            int s2 = __ldg(d_csrc_i + p + 2);
            int s3 = __ldg(d_csrc_i + p + 3);
            float w0 = __ldg(d_cw_i + p);
            float w1 = __ldg(d_cw_i + p + 1);
            float w2 = __ldg(d_cw_i + p + 2);
            float w3 = __ldg(d_cw_i + p + 3);
            float4 h0 = *(const float4*)(hin + (size_t)s0 * HD + lane * 4);
            float4 h1 = *(const float4*)(hin + (size_t)s1 * HD + lane * 4);
            float4 h2 = *(const float4*)(hin + (size_t)s2 * HD + lane * 4);
            float4 h3 = *(const float4*)(hin + (size_t)s3 * HD + lane * 4);
            a0.x += h0.x * w0; a0.y += h0.y * w0; a0.z += h0.z * w0; a0.w += h0.w * w0;
            a1.x += h1.x * w1; a1.y += h1.y * w1; a1.z += h1.z * w1; a1.w += h1.w * w1;
            a0.x += h2.x * w2; a0.y += h2.y * w2; a0.z += h2.z * w2; a0.w += h2.w * w2;
            a1.x += h3.x * w3; a1.y += h3.y * w3; a1.z += h3.z * w3; a1.w += h3.w * w3;
        }
        for (; p < pe; p++) {
            int s0 = __ldg(d_csrc_i + p);
            float w0 = __ldg(d_cw_i + p);
            float4 h0 = *(const float4*)(hin + (size_t)s0 * HD + lane * 4);
            a0.x += h0.x * w0; a0.y += h0.y * w0; a0.z += h0.z * w0; a0.w += h0.w * w0;
        }
        *(float4*)(d_aggi + (size_t)n * HD + lane * 4) =
            make_float4(a0.x + a1.x, a0.y + a1.y, a0.z + a1.z, a0.w + a1.w);
    }
    // inter
    {
        int p = d_off_e[n], pe = d_off_e[n + 1];
        float4 a0 = {0, 0, 0, 0}, a1 = {0, 0, 0, 0};
        for (; p + 4 <= pe; p += 4) {
            int s0 = __ldg(d_csrc_e + p);
            int s1 = __ldg(d_csrc_e + p + 1);
            int s2 = __ldg(d_csrc_e + p + 2);
            int s3 = __ldg(d_csrc_e + p + 3);
            float w0 = __ldg(d_cw_e + p);
            float w1 = __ldg(d_cw_e + p + 1);
            float w2 = __ldg(d_cw_e + p + 2);
            float w3 = __ldg(d_cw_e + p + 3);
            float4 h0 = *(const float4*)(hin + (size_t)s0 * HD + lane * 4);
            float4 h1 = *(const float4*)(hin + (size_t)s1 * HD + lane * 4);
            float4 h2 = *(const float4*)(hin + (size_t)s2 * HD + lane * 4);
            float4 h3 = *(const float4*)(hin + (size_t)s3 * HD + lane * 4);
            a0.x += h0.x * w0; a0.y += h0.y * w0; a0.z += h0.z * w0; a0.w += h0.w * w0;
            a1.x += h1.x * w1; a1.y += h1.y * w1; a1.z += h1.z * w1; a1.w += h1.w * w1;
            a0.x += h2.x * w2; a0.y += h2.y * w2; a0.z += h2.z * w2; a0.w += h2.w * w2;
            a1.x += h3.x * w3; a1.y += h3.y * w3; a1.z += h3.z * w3; a1.w += h3.w * w3;
        }
        for (; p < pe; p++) {
            int s0 = __ldg(d_csrc_e + p);
            float w0 = __ldg(d_cw_e + p);
            float4 h0 = *(const float4*)(hin + (size_t)s0 * HD + lane * 4);
            a0.x += h0.x * w0; a0.y += h0.y * w0; a0.z += h0.z * w0; a0.w += h0.w * w0;
        }
        *(float4*)(d_agge + (size_t)n * HD + lane * 4) =
            make_float4(a0.x + a1.x, a0.y + a1.y, a0.z + a1.z, a0.w + a1.w);
    }
}

// ---------------- mma.sync dual GEMM (bf16 x3 split) + SiLU state update ----------------
// 64 node-rows per block, 256 threads = 8 warps = 4 row-strips(m16) x 2 col-halves(n64).
// Padded smem rows: 36 words (32 data + 4 skew) -> conflict-free frag loads.
// smem words: bias[256] | A pieces 4 x 64x36 | W pieces 4 x 128x36
#define AWOFF(mp) (256 + (mp) * 2304)
#define WWOFF(mp) (9472 + (mp) * 4608)
#define UPD_SMEM 111616

__global__ __launch_bounds__(256, 2)
void k_updmma(const float* __restrict__ bi, const float* __restrict__ be,
              const int* __restrict__ batch, int layer, int parity, int last) {
    extern __shared__ unsigned swm[];
    float* sbias = (float*)swm;
    int t = threadIdx.x, lane = t & 31, wid = t >> 5;
    int n0 = blockIdx.x * 64;
    const float* __restrict__ hin = parity ? d_h2 : d_h;
    float* hout = parity ? d_h : d_h2;

    if (t < 128) sbias[t] = bi[t];
    else sbias[t] = be[t - 128];

    float acc_i[8][4], acc_e[8][4];
#pragma unroll
    for (int tt = 0; tt < 8; tt++)
#pragma unroll
        for (int q = 0; q < 4; q++) { acc_i[tt][q] = 0.f; acc_e[tt][q] = 0.f; }

    int strip = wid >> 1, half = wid & 1;
    int row = t >> 2, seg = t & 3;
    unsigned arowb = (unsigned)((strip * 16 + (lane >> 2)) * 36 + (lane & 3));
    unsigned browb = (unsigned)((half * 64 + (lane >> 2)) * 36 + (lane & 3));

    for (int c = 0; c < 2; c++) {
        __syncthreads();
        // ---- stage A: fp32 agg -> bf16 hi/lo ----
#pragma unroll
        for (int m = 0; m < 2; m++) {
            const float* src = (m ? d_agge : d_aggi) + (size_t)(n0 + row) * HD + c * 64 + seg * 16;
            unsigned hb = AWOFF(m * 2) + row * 36 + seg * 8;
            unsigned lb = AWOFF(m * 2 + 1) + row * 36 + seg * 8;
#pragma unroll
            for (int q = 0; q < 4; q++) {
                float4 v = ((const float4*)src)[q];
                unsigned wh0 = bf16x2_of(v.x, v.y);
                float r0 = v.x - __uint_as_float(wh0 << 16);
                float r1 = v.y - __uint_as_float(wh0 & 0xffff0000u);
                unsigned wl0 = bf16x2_of(r0, r1);
                unsigned wh1 = bf16x2_of(v.z, v.w);
                float r2 = v.z - __uint_as_float(wh1 << 16);
                float r3 = v.w - __uint_as_float(wh1 & 0xffff0000u);
                unsigned wl1 = bf16x2_of(r2, r3);
                swm[hb + q * 2]     = wh0;
                swm[hb + q * 2 + 1] = wh1;
                swm[lb + q * 2]     = wl0;
                swm[lb + q * 2 + 1] = wl1;
            }
        }
        // ---- stage W: copy prepped image chunk ----
#pragma unroll
        for (int mp = 0; mp < 4; mp++) {
            unsigned pbase = (unsigned)(layer * 4 + mp) * 8192 + c * 32;
#pragma unroll
            for (int uu = 0; uu < 4; uu++) {
                int u = t + uu * 256;
                int nrow = u >> 3, s = u & 7;
                int4 v = *(const int4*)(d_wimg + pbase + nrow * 64 + s * 4);
                *(int4*)(swm + WWOFF(mp) + nrow * 36 + s * 4) = v;
            }
        }
        __syncthreads();
        // ---- compute: 4 k-steps of 16 ----
#pragma unroll
        for (int s = 0; s < 4; s++) {
            unsigned ko = s * 8;
            unsigned a_ih[4], a_il[4], a_eh[4], a_el[4];
            a_ih[0] = swm[AWOFF(0) + arowb + ko];
            a_ih[1] = swm[AWOFF(0) + arowb + 288 + ko];
            a_ih[2] = swm[AWOFF(0) + arowb + ko + 4];
            a_ih[3] = swm[AWOFF(0) + arowb + 288 + ko + 4];
            a_il[0] = swm[AWOFF(1) + arowb + ko];
            a_il[1] = swm[AWOFF(1) + arowb + 288 + ko];
            a_il[2] = swm[AWOFF(1) + arowb + ko + 4];
            a_il[3] = swm[AWOFF(1) + arowb + 288 + ko + 4];
            a_eh[0] = swm[AWOFF(2) + arowb + ko];
            a_eh[1] = swm[AWOFF(2) + arowb + 288 + ko];
            a_eh[2] = swm[AWOFF(2) + arowb + ko + 4];
            a_eh[3] = swm[AWOFF(2) + arowb + 288 + ko + 4];
            a_el[0] = swm[AWOFF(3) + arowb + ko];
            a_el[1] = swm[AWOFF(3) + arowb + 288 + ko];
            a_el[2] = swm[AWOFF(3) + arowb + ko + 4];
            a_el[3] = swm[AWOFF(3) + arowb + 288 + ko + 4];
#pragma unroll
            for (int tt = 0; tt < 8; tt++) {
                unsigned bo = browb + tt * 288 + ko;
                unsigned bb[2];
                bb[0] = swm[WWOFF(0) + bo]; bb[1] = swm[WWOFF(0) + bo + 4];
                mma16816(acc_i[tt], a_ih, bb);
                mma16816(acc_i[tt], a_il, bb);
                bb[0] = swm[WWOFF(1) + bo]; bb[1] = swm[WWOFF(1) + bo + 4];
                mma16816(acc_i[tt], a_ih, bb);
                bb[0] = swm[WWOFF(2) + bo]; bb[1] = swm[WWOFF(2) + bo + 4];
                mma16816(acc_e[tt], a_eh, bb);
                mma16816(acc_e[tt], a_el, bb);
                bb[0] = swm[WWOFF(3) + bo]; bb[1] = swm[WWOFF(3) + bo + 4];
                mma16816(acc_e[tt], a_eh, bb);
            }
        }
    }

    // ---- epilogue ----
#pragma unroll
    for (int rr = 0; rr < 2; rr++) {
        int n = n0 + strip * 16 + (lane >> 2) + rr * 8;
        if (n >= NN) continue;
        float ci = d_cnti[n], inv = d_invi[n];
        float ce = d_cnte[n], lge = d_loge[n];
        int bb = last ? __ldg(batch + n) : 0;
#pragma unroll
        for (int tt = 0; tt < 8; tt++) {
            int cc = half * 64 + tt * 8 + (lane & 3) * 2;
            size_t off = (size_t)n * HD + cc;
            float2 vp = *(const float2*)(d_vp + off);
            float2 vl = *(const float2*)(d_vl + off);
            float2 hh = *(const float2*)(hin + off);
            float mi0 = acc_i[tt][rr * 2], mi1 = acc_i[tt][rr * 2 + 1];
            float me0 = acc_e[tt][rr * 2], me1 = acc_e[tt][rr * 2 + 1];
            float m10 = (mi0 + ci * sbias[cc]) * inv;
            float m11 = (mi1 + ci * sbias[cc + 1]) * inv;
            float m20 = (me0 + ce * sbias[128 + cc]) * lge;
            float m21 = (me1 + ce * sbias[128 + cc + 1]) * lge;
            float p0 = siluf(m10 + vp.x), p1 = siluf(m11 + vp.y);
            float l0 = siluf(m20 + vl.x), l1 = siluf(m21 + vl.y);
            float h0 = hh.x + p0 + l0, h1 = hh.y + p1 + l1;
            *(float2*)(d_vp + off) = make_float2(p0, p1);
            *(float2*)(d_vl + off) = make_float2(l0, l1);
            *(float2*)(hout + off) = make_float2(h0, h1);
            if (last) {
                float* pp = d_pool + bb * HD + cc;
                asm volatile("red.global.add.f32 [%0], %1;" :: "l"(pp), "f"(h0) : "memory");
                asm volatile("red.global.add.f32 [%0], %1;" :: "l"(pp + 1), "f"(h1) : "memory");
            }
        }
    }
}

// ---------------- FC head ----------------
__global__ __launch_bounds__(128) void k_fc(const float* __restrict__ W,
                                            const float* __restrict__ b,
                                            const float* __restrict__ gam,
                                            const float* __restrict__ bet,
                                            int swap) {
    __shared__ float gr[HD];
    int bid = blockIdx.x;
    int t = threadIdx.x;
    const float* gin = swap ? d_fcbuf : d_pool;
    float* gout = swap ? d_pool : d_fcbuf;
    gr[t] = gin[bid * HD + t];
    __syncthreads();
    float acc = b[t];
#pragma unroll 8
    for (int k = 0; k < HD; k++) acc += gr[k] * W[k * HD + t];
    acc = acc > 0.f ? acc : 0.01f * acc;
    float bnscale = rsqrtf(1.0f + 1e-5f);
    acc = acc * bnscale * gam[t] + bet[t];
    gout[bid * HD + t] = acc;
}

__global__ __launch_bounds__(128) void k_out(const float* __restrict__ oW,
                                             const float* __restrict__ ob,
                                             float* __restrict__ out) {
    __shared__ float part[4];
    int b = blockIdx.x;
    int t = threadIdx.x;
    float p = d_fcbuf[b * HD + t] * oW[t];
#pragma unroll
    for (int o = 16; o > 0; o >>= 1) p += __shfl_down_sync(0xffffffffu, p, o);
    if ((t & 31) == 0) part[t >> 5] = p;
    __syncthreads();
    if (t == 0) out[b] = part[0] + part[1] + part[2] + part[3] + ob[0];
}

// ---------------- host launcher ----------------
extern "C" void kernel_launch(void* const* d_in, const int* in_sizes, int n_in,
                              void* d_out, int out_size) {
    const float* x     = (const float*)d_in[0];
    const int*   ei    = (const int*)d_in[1];
    const int*   ee    = (const int*)d_in[2];
    const float* pos   = (const float*)d_in[3];
    const float* eattr = (const float*)d_in[4];
    const int*   batch = (const int*)d_in[5];
    const float* lnW   = (const float*)d_in[6];
    const float* lnb   = (const float*)d_in[7];
    const float* Wi    = (const float*)d_in[8];
    const float* bi    = (const float*)d_in[9];
    const float* We    = (const float*)d_in[10];
    const float* be    = (const float*)d_in[11];
    const float* fcW   = (const float*)d_in[12];
    const float* fcb   = (const float*)d_in[13];
    const float* gam   = (const float*)d_in[14];
    const float* bet   = (const float*)d_in[15];
    const float* oW    = (const float*)d_in[16];
    const float* ob    = (const float*)d_in[17];
    float* out = (float*)d_out;

    static int smem_set = 0;
    if (!smem_set) {
        cudaFuncSetAttribute(k_updmma, cudaFuncAttributeMaxDynamicSharedMemorySize, UPD_SMEM);
        smem_set = 1;
    }

    k_zero_pre<<<(NN + 255) / 256, 256>>>();
    k_linnode<<<NN / 8, 128>>>(x, lnW, lnb);
    k_deg_intra<<<(EI + 255) / 256, 256>>>(ei);
    k_deg_inter<<<(EE + 255) / 256, 256>>>(ee, pos);
    k_prepw<<<256, 256>>>(Wi, We);

    k_scan_a<<<NBLK_SCAN, 1024>>>(0);
    k_scan_a<<<NBLK_SCAN, 1024>>>(1);
    k_scan_b<<<1, 32>>>();
    k_scan_c<<<NBLK_SCAN, 1024>>>(0);
    k_scan_c<<<NBLK_SCAN, 1024>>>(1);
    k_factors<<<(NN + 255) / 256, 256>>>();
    k_fill_i<<<(EI + 255) / 256, 256>>>(ei, eattr);
    k_fill_e<<<(EE + 255) / 256, 256>>>(ee);

    for (int l = 0; l < 4; l++) {
        k_gather<<<(NN * 32 + 255) / 256, 256>>>(l & 1);
        k_updmma<<<NBLK_UPD, 256, UPD_SMEM>>>(bi + l * HD, be + l * HD, batch, l, l & 1, l == 3);
    }

    k_fc<<<GB, 128>>>(fcW + 0 * HD * HD, fcb + 0 * HD, gam + 0 * HD, bet + 0 * HD, 0);
    k_fc<<<GB, 128>>>(fcW + 1 * HD * HD, fcb + 1 * HD, gam + 1 * HD, bet + 1 * HD, 1);
    k_fc<<<GB, 128>>>(fcW + 2 * HD * HD, fcb + 2 * HD, gam + 2 * HD, bet + 2 * HD, 0);
    k_out<<<GB, 128>>>(oW, ob, out);
}

// round 10
// speedup vs baseline: 2.3495x; 1.0214x over previous
#include <cuda_runtime.h>
#include <cuda_bf16.h>
#include <math.h>

#define NN 100000
#define NP 100096          // padded ( >= 1563*64 = 100032 )
#define NBLK_UPD 1563
#define EI 800000
#define EE 400000
#define HD 128
#define GB 256
#define ND 35
#define NBLK_SCAN 98       // ceil(100000/1024)

typedef unsigned long long ull;

// ---------------- device scratch ----------------
__device__ float d_h [NN * HD];
__device__ float d_h2[NN * HD];
__device__ float d_vp[NN * HD];
__device__ float d_vl[NN * HD];
__device__ float d_yi[NP * HD];     // h @ W_intra
__device__ float d_ye[NP * HD];     // h @ W_inter
__device__ float d_wint[EE];
__device__ int   d_ecnt_i[NN];
__device__ int   d_ecnt_e[NN];
__device__ int   d_fill_i[NN];
__device__ int   d_fill_e[NN];
__device__ int   d_off_i[NN + 1];
__device__ int   d_off_e[NN + 1];
__device__ int   d_bsum_i[NBLK_SCAN];
__device__ int   d_bsum_e[NBLK_SCAN];
__device__ int   d_csrc_i[EI];
__device__ float d_cw_i[EI];
__device__ int   d_csrc_e[EE];
__device__ float d_cw_e[EE];
__device__ float d_cnti[NN];
__device__ float d_cnte[NN];
__device__ float d_invi[NN];
__device__ float d_loge[NN];
__device__ float d_pool[GB * HD];
__device__ float d_fcbuf[GB * HD];
// weight image: bf16 hi/lo split, transposed [n][k] pairs packed in 32-bit words.
// piece index pb = layer*4 + mat*2 + (0=hi,1=lo); each piece = 128 n-rows x 64 k-words.
__device__ unsigned d_wimg[4 * 2 * 2 * 128 * 64];

// ---------------- helpers ----------------
__device__ __forceinline__ float siluf(float v) { return v / (1.0f + expf(-v)); }

__device__ __forceinline__ void red_add_v4(float* p, float4 v) {
    asm volatile("red.global.add.v4.f32 [%0], {%1,%2,%3,%4};"
                 :: "l"(p), "f"(v.x), "f"(v.y), "f"(v.z), "f"(v.w) : "memory");
}

// d = {hi=bf16(a1), lo=bf16(a0)}
__device__ __forceinline__ unsigned bf16x2_of(float a0, float a1) {
    unsigned w;
    asm("cvt.rn.bf16x2.f32 %0, %1, %2;" : "=r"(w) : "f"(a1), "f"(a0));
    return w;
}

__device__ __forceinline__ void mma16816(float* d, const unsigned* a, const unsigned* b) {
    asm volatile("mma.sync.aligned.m16n8k16.row.col.f32.bf16.bf16.f32 "
                 "{%0,%1,%2,%3}, {%4,%5,%6,%7}, {%8,%9}, {%0,%1,%2,%3};"
                 : "+f"(d[0]), "+f"(d[1]), "+f"(d[2]), "+f"(d[3])
                 : "r"(a[0]), "r"(a[1]), "r"(a[2]), "r"(a[3]), "r"(b[0]), "r"(b[1]));
}

// ---------------- init ----------------
__global__ void k_zero_pre() {
    int i = blockIdx.x * blockDim.x + threadIdx.x;
    if (i < NN) {
        d_ecnt_i[i] = 0; d_ecnt_e[i] = 0;
        d_fill_i[i] = 0; d_fill_e[i] = 0;
    }
    if (i < GB * HD) d_pool[i] = 0.0f;
}

// lin_node: h = silu(x @ W + b); vp = vl = 0
__global__ __launch_bounds__(128) void k_linnode(const float* __restrict__ x,
                                                 const float* __restrict__ W,
                                                 const float* __restrict__ b) {
    __shared__ float Ws[ND * HD];
    __shared__ float xs[8][ND];
    int t = threadIdx.x;
    for (int i = t; i < ND * HD; i += 128) Ws[i] = W[i];
    int n0 = blockIdx.x * 8;
    for (int i = t; i < 8 * ND; i += 128) {
        int nn = i / ND, k = i % ND;
        xs[nn][k] = x[(n0 + nn) * ND + k];
    }
    __syncthreads();
    float bb = b[t];
    for (int nn = 0; nn < 8; nn++) {
        int n = n0 + nn;
        float acc = bb;
#pragma unroll
        for (int k = 0; k < ND; k++) acc += xs[nn][k] * Ws[k * HD + t];
        d_h[n * HD + t] = siluf(acc);
        d_vp[n * HD + t] = 0.0f;
        d_vl[n * HD + t] = 0.0f;
    }
}

// ---------------- degrees + geometric weights (merged) ----------------
__global__ void k_deg(const int* __restrict__ ei, const int* __restrict__ ee,
                      const float* __restrict__ pos) {
    int e = blockIdx.x * blockDim.x + threadIdx.x;
    if (e < EI) atomicAdd(&d_ecnt_i[ei[EI + e]], 1);
    if (e < EE) {
        int s = ee[e], d = ee[EE + e];
        float dx = pos[s * 3 + 0] - pos[d * 3 + 0];
        float dy = pos[s * 3 + 1] - pos[d * 3 + 1];
        float dz = pos[s * 3 + 2] - pos[d * 3 + 2];
        d_wint[e] = expf(-(dx * dx + dy * dy + dz * dz));
        atomicAdd(&d_ecnt_e[d], 1);
    }
}

// ---------------- prefix scan (exclusive) -> CSR offsets ----------------
__global__ __launch_bounds__(1024) void k_scan_a(int which) {
    __shared__ int sh[1024];
    const int* cnt = which ? d_ecnt_e : d_ecnt_i;
    int* off = which ? d_off_e : d_off_i;
    int* bs  = which ? d_bsum_e : d_bsum_i;
    int tid = threadIdx.x;
    int i = blockIdx.x * 1024 + tid;
    int v = (i < NN) ? cnt[i] : 0;
    sh[tid] = v;
    __syncthreads();
#pragma unroll
    for (int o = 1; o < 1024; o <<= 1) {
        int u = (tid >= o) ? sh[tid - o] : 0;
        __syncthreads();
        sh[tid] += u;
        __syncthreads();
    }
    if (i <= NN) off[i] = sh[tid] - v;  // exclusive
    if (tid == 1023) bs[blockIdx.x] = sh[1023];
}

__global__ void k_scan_b() {
    if (threadIdx.x == 0) {
        int r = 0;
        for (int b = 0; b < NBLK_SCAN; b++) { int t = d_bsum_i[b]; d_bsum_i[b] = r; r += t; }
    }
    if (threadIdx.x == 1) {
        int r = 0;
        for (int b = 0; b < NBLK_SCAN; b++) { int t = d_bsum_e[b]; d_bsum_e[b] = r; r += t; }
    }
}

__global__ __launch_bounds__(1024) void k_scan_c(int which) {
    int* off = which ? d_off_e : d_off_i;
    const int* bs = which ? d_bsum_e : d_bsum_i;
    int i = blockIdx.x * 1024 + threadIdx.x;
    if (i <= NN) off[i] += bs[blockIdx.x];
}

// ---------------- CSR fill + degree factors (merged) ----------------
__global__ void k_fillf(const int* __restrict__ ei, const int* __restrict__ ee,
                        const float* __restrict__ ea) {
    int e = blockIdx.x * blockDim.x + threadIdx.x;
    if (e < NN) {
        float ci = (float)d_ecnt_i[e];
        float ce = (float)d_ecnt_e[e];
        d_cnti[e] = ci;
        d_cnte[e] = ce;
        d_invi[e] = 1.0f / (ci + 1.0f);
        d_loge[e] = logf(ce + 1.0f);
    }
    if (e < EI) {
        int s = ei[e], d = ei[EI + e];
        int p = d_off_i[d] + atomicAdd(&d_fill_i[d], 1);
        d_csrc_i[p] = s;
        d_cw_i[p] = ea[e];
    }
    if (e < EE) {
        int s = ee[e], d = ee[EE + e];
        int p = d_off_e[d] + atomicAdd(&d_fill_e[d], 1);
        d_csrc_e[p] = s;
        d_cw_e[p] = d_wint[e];
    }
}

// ---------------- weight prep: transpose + bf16 hi/lo split (once) ----------------
__global__ void k_prepw(const float* __restrict__ Wi, const float* __restrict__ We) {
    int gid = blockIdx.x * blockDim.x + threadIdx.x;
    if (gid >= 65536) return;
    int j = gid & 63;            // k-pair word
    int n = (gid >> 6) & 127;    // output col = B n-row
    int m = (gid >> 13) & 1;
    int l = gid >> 14;
    const float* Wsrc = (m ? We : Wi) + l * HD * HD;
    int k0 = 2 * j;
    float w0 = Wsrc[k0 * HD + n];
    float w1 = Wsrc[(k0 + 1) * HD + n];
    unsigned wh = bf16x2_of(w0, w1);
    float r0 = w0 - __uint_as_float(wh << 16);
    float r1 = w1 - __uint_as_float(wh & 0xffff0000u);
    unsigned wl = bf16x2_of(r0, r1);
    int pb = l * 4 + m * 2;
    d_wimg[(size_t)pb * 8192 + n * 64 + j] = wh;
    d_wimg[(size_t)(pb + 1) * 8192 + n * 64 + j] = wl;
}

// ---------------- k_trans: dense dual GEMM yi = h@Wi, ye = h@We (bf16 x3 split) ----------------
// 64 node-rows per block, 256 threads = 8 warps = 4 row-strips(m16) x 2 col-halves(n64).
#define AWOFF(mp) (256 + (mp) * 2304)
#define WWOFF(mp) (9472 + (mp) * 4608)
#define UPD_SMEM 111616

__global__ __launch_bounds__(256, 2)
void k_trans(int layer, int parity) {
    extern __shared__ unsigned swm[];
    int t = threadIdx.x, lane = t & 31, wid = t >> 5;
    int n0 = blockIdx.x * 64;
    const float* __restrict__ hin = parity ? d_h2 : d_h;

    float acc_i[8][4], acc_e[8][4];
#pragma unroll
    for (int tt = 0; tt < 8; tt++)
#pragma unroll
        for (int q = 0; q < 4; q++) { acc_i[tt][q] = 0.f; acc_e[tt][q] = 0.f; }

    int strip = wid >> 1, half = wid & 1;
    int row = t >> 2, seg = t & 3;
    unsigned arowb = (unsigned)((strip * 16 + (lane >> 2)) * 36 + (lane & 3));
    unsigned browb = (unsigned)((half * 64 + (lane >> 2)) * 36 + (lane & 3));
    int nclamp = n0 + row < NN ? n0 + row : NN - 1;   // clamp tail rows (results discarded)

    for (int c = 0; c < 2; c++) {
        __syncthreads();
        // ---- stage A: fp32 h -> bf16 hi/lo (both A-piece slots 0/1 used for h; 2/3 alias) ----
        {
            const float* src = hin + (size_t)nclamp * HD + c * 64 + seg * 16;
            unsigned hb = AWOFF(0) + row * 36 + seg * 8;
            unsigned lb = AWOFF(1) + row * 36 + seg * 8;
#pragma unroll
            for (int q = 0; q < 4; q++) {
                float4 v = ((const float4*)src)[q];
                unsigned wh0 = bf16x2_of(v.x, v.y);
                float r0 = v.x - __uint_as_float(wh0 << 16);
                float r1 = v.y - __uint_as_float(wh0 & 0xffff0000u);
                unsigned wl0 = bf16x2_of(r0, r1);
                unsigned wh1 = bf16x2_of(v.z, v.w);
                float r2 = v.z - __uint_as_float(wh1 << 16);
                float r3 = v.w - __uint_as_float(wh1 & 0xffff0000u);
                unsigned wl1 = bf16x2_of(r2, r3);
                swm[hb + q * 2]     = wh0;
                swm[hb + q * 2 + 1] = wh1;
                swm[lb + q * 2]     = wl0;
                swm[lb + q * 2 + 1] = wl1;
            }
        }
        // ---- stage W: copy prepped image chunk ----
#pragma unroll
        for (int mp = 0; mp < 4; mp++) {
            unsigned pbase = (unsigned)(layer * 4 + mp) * 8192 + c * 32;
#pragma unroll
            for (int uu = 0; uu < 4; uu++) {
                int u = t + uu * 256;
                int nrow = u >> 3, s = u & 7;
                int4 v = *(const int4*)(d_wimg + pbase + nrow * 64 + s * 4);
                *(int4*)(swm + WWOFF(mp) + nrow * 36 + s * 4) = v;
            }
        }
        __syncthreads();
        // ---- compute: 4 k-steps of 16 ----
#pragma unroll
        for (int s = 0; s < 4; s++) {
            unsigned ko = s * 8;
            unsigned a_h[4], a_l[4];
            a_h[0] = swm[AWOFF(0) + arowb + ko];
            a_h[1] = swm[AWOFF(0) + arowb + 288 + ko];
            a_h[2] = swm[AWOFF(0) + arowb + ko + 4];
            a_h[3] = swm[AWOFF(0) + arowb + 288 + ko + 4];
            a_l[0] = swm[AWOFF(1) + arowb + ko];
            a_l[1] = swm[AWOFF(1) + arowb + 288 + ko];
            a_l[2] = swm[AWOFF(1) + arowb + ko + 4];
            a_l[3] = swm[AWOFF(1) + arowb + 288 + ko + 4];
#pragma unroll
            for (int tt = 0; tt < 8; tt++) {
                unsigned bo = browb + tt * 288 + ko;
                unsigned bb[2];
                bb[0] = swm[WWOFF(0) + bo]; bb[1] = swm[WWOFF(0) + bo + 4];
                mma16816(acc_i[tt], a_h, bb);
                mma16816(acc_i[tt], a_l, bb);
                bb[0] = swm[WWOFF(1) + bo]; bb[1] = swm[WWOFF(1) + bo + 4];
                mma16816(acc_i[tt], a_h, bb);
                bb[0] = swm[WWOFF(2) + bo]; bb[1] = swm[WWOFF(2) + bo + 4];
                mma16816(acc_e[tt], a_h, bb);
                mma16816(acc_e[tt], a_l, bb);
                bb[0] = swm[WWOFF(3) + bo]; bb[1] = swm[WWOFF(3) + bo + 4];
                mma16816(acc_e[tt], a_h, bb);
            }
        }
    }

    // ---- store yi/ye (padded arrays: rows up to NP are safe) ----
#pragma unroll
    for (int rr = 0; rr < 2; rr++) {
        int n = n0 + strip * 16 + (lane >> 2) + rr * 8;
#pragma unroll
        for (int tt = 0; tt < 8; tt++) {
            int cc = half * 64 + tt * 8 + (lane & 3) * 2;
            size_t off = (size_t)n * HD + cc;
            *(float2*)(d_yi + off) = make_float2(acc_i[tt][rr * 2], acc_i[tt][rr * 2 + 1]);
            *(float2*)(d_ye + off) = make_float2(acc_e[tt][rr * 2], acc_e[tt][rr * 2 + 1]);
        }
    }
}

// ---------------- k_gath2: CSR gather of yi/ye + full epilogue ----------------
__global__ __launch_bounds__(256) void k_gath2(const float* __restrict__ bi,
                                               const float* __restrict__ be,
                                               const int* __restrict__ batch,
                                               int parity, int last) {
    int g = blockIdx.x * 256 + threadIdx.x;
    int n = g >> 5;
    int lane = g & 31;
    if (n >= NN) return;
    const float* __restrict__ hin = parity ? d_h2 : d_h;
    float* hout = parity ? d_h : d_h2;

    float4 si, se;
    // intra gather from yi
    {
        int p = d_off_i[n], pe = d_off_i[n + 1];
        float4 a0 = {0, 0, 0, 0}, a1 = {0, 0, 0, 0};
        for (; p + 4 <= pe; p += 4) {
            int s0 = __ldg(d_csrc_i + p);
            int s1 = __ldg(d_csrc_i + p + 1);
            int s2 = __ldg(d_csrc_i + p + 2);
            int s3 = __ldg(d_csrc_i + p + 3);
            float w0 = __ldg(d_cw_i + p);
            float w1 = __ldg(d_cw_i + p + 1);
            float w2 = __ldg(d_cw_i + p + 2);
            float w3 = __ldg(d_cw_i + p + 3);
            float4 h0 = *(const float4*)(d_yi + (size_t)s0 * HD + lane * 4);
            float4 h1 = *(const float4*)(d_yi + (size_t)s1 * HD + lane * 4);
            float4 h2 = *(const float4*)(d_yi + (size_t)s2 * HD + lane * 4);
            float4 h3 = *(const float4*)(d_yi + (size_t)s3 * HD + lane * 4);
            a0.x += h0.x * w0; a0.y += h0.y * w0; a0.z += h0.z * w0; a0.w += h0.w * w0;
            a1.x += h1.x * w1; a1.y += h1.y * w1; a1.z += h1.z * w1; a1.w += h1.w * w1;
            a0.x += h2.x * w2; a0.y += h2.y * w2; a0.z += h2.z * w2; a0.w += h2.w * w2;
            a1.x += h3.x * w3; a1.y += h3.y * w3; a1.z += h3.z * w3; a1.w += h3.w * w3;
        }
        for (; p < pe; p++) {
            int s0 = __ldg(d_csrc_i + p);
            float w0 = __ldg(d_cw_i + p);
            float4 h0 = *(const float4*)(d_yi + (size_t)s0 * HD + lane * 4);
            a0.x += h0.x * w0; a0.y += h0.y * w0; a0.z += h0.z * w0; a0.w += h0.w * w0;
        }
        si = make_float4(a0.x + a1.x, a0.y + a1.y, a0.z + a1.z, a0.w + a1.w);
    }
    // inter gather from ye
    {
        int p = d_off_e[n], pe = d_off_e[n + 1];
        float4 a0 = {0, 0, 0, 0}, a1 = {0, 0, 0, 0};
        for (; p + 4 <= pe; p += 4) {
            int s0 = __ldg(d_csrc_e + p);
            int s1 = __ldg(d_csrc_e + p + 1);
            int s2 = __ldg(d_csrc_e + p + 2);
            int s3 = __ldg(d_csrc_e + p + 3);
            float w0 = __ldg(d_cw_e + p);
            float w1 = __ldg(d_cw_e + p + 1);
            float w2 = __ldg(d_cw_e + p + 2);
            float w3 = __ldg(d_cw_e + p + 3);
            float4 h0 = *(const float4*)(d_ye + (size_t)s0 * HD + lane * 4);
            float4 h1 = *(const float4*)(d_ye + (size_t)s1 * HD + lane * 4);
            float4 h2 = *(const float4*)(d_ye + (size_t)s2 * HD + lane * 4);
            float4 h3 = *(const float4*)(d_ye + (size_t)s3 * HD + lane * 4);
            a0.x += h0.x * w0; a0.y += h0.y * w0; a0.z += h0.z * w0; a0.w += h0.w * w0;
            a1.x += h1.x * w1; a1.y += h1.y * w1; a1.z += h1.z * w1; a1.w += h1.w * w1;
            a0.x += h2.x * w2; a0.y += h2.y * w2; a0.z += h2.z * w2; a0.w += h2.w * w2;
            a1.x += h3.x * w3; a1.y += h3.y * w3; a1.z += h3.z * w3; a1.w += h3.w * w3;
        }
        for (; p < pe; p++) {
            int s0 = __ldg(d_csrc_e + p);
            float w0 = __ldg(d_cw_e + p);
            float4 h0 = *(const float4*)(d_ye + (size_t)s0 * HD + lane * 4);
            a0.x += h0.x * w0; a0.y += h0.y * w0; a0.z += h0.z * w0; a0.w += h0.w * w0;
        }
        se = make_float4(a0.x + a1.x, a0.y + a1.y, a0.z + a1.z, a0.w + a1.w);
    }

    // epilogue
    float ci = __ldg(d_cnti + n), inv = __ldg(d_invi + n);
    float ce = __ldg(d_cnte + n), lge = __ldg(d_loge + n);
    float4 bi4 = *(const float4*)(bi + lane * 4);
    float4 be4 = *(const float4*)(be + lane * 4);
    size_t off = (size_t)n * HD + lane * 4;
    float4 vp = *(const float4*)(d_vp + off);
    float4 vl = *(const float4*)(d_vl + off);
    float4 hh = *(const float4*)(hin + off);

    float p0 = siluf((si.x + ci * bi4.x) * inv + vp.x);
    float p1 = siluf((si.y + ci * bi4.y) * inv + vp.y);
    float p2 = siluf((si.z + ci * bi4.z) * inv + vp.z);
    float p3 = siluf((si.w + ci * bi4.w) * inv + vp.w);
    float l0 = siluf((se.x + ce * be4.x) * lge + vl.x);
    float l1 = siluf((se.y + ce * be4.y) * lge + vl.y);
    float l2 = siluf((se.z + ce * be4.z) * lge + vl.z);
    float l3 = siluf((se.w + ce * be4.w) * lge + vl.w);
    float4 ho = make_float4(hh.x + p0 + l0, hh.y + p1 + l1, hh.z + p2 + l2, hh.w + p3 + l3);

    if (!last) {
        *(float4*)(d_vp + off) = make_float4(p0, p1, p2, p3);
        *(float4*)(d_vl + off) = make_float4(l0, l1, l2, l3);
        *(float4*)(hout + off) = ho;
    } else {
        int bb = __ldg(batch + n);
        red_add_v4(d_pool + bb * HD + lane * 4, ho);
    }
}

// ---------------- FC head ----------------
__global__ __launch_bounds__(128) void k_fc(const float* __restrict__ W,
                                            const float* __restrict__ b,
                                            const float* __restrict__ gam,
                                            const float* __restrict__ bet,
                                            int swap) {
    __shared__ float gr[HD];
    int bid = blockIdx.x;
    int t = threadIdx.x;
    const float* gin = swap ? d_fcbuf : d_pool;
    float* gout = swap ? d_pool : d_fcbuf;
    gr[t] = gin[bid * HD + t];
    __syncthreads();
    float acc = b[t];
#pragma unroll 8
    for (int k = 0; k < HD; k++) acc += gr[k] * W[k * HD + t];
    acc = acc > 0.f ? acc : 0.01f * acc;
    float bnscale = rsqrtf(1.0f + 1e-5f);
    acc = acc * bnscale * gam[t] + bet[t];
    gout[bid * HD + t] = acc;
}

__global__ __launch_bounds__(128) void k_out(const float* __restrict__ oW,
                                             const float* __restrict__ ob,
                                             float* __restrict__ out) {
    __shared__ float part[4];
    int b = blockIdx.x;
    int t = threadIdx.x;
    float p = d_fcbuf[b * HD + t] * oW[t];
#pragma unroll
    for (int o = 16; o > 0; o >>= 1) p += __shfl_down_sync(0xffffffffu, p, o);
    if ((t & 31) == 0) part[t >> 5] = p;
    __syncthreads();
    if (t == 0) out[b] = part[0] + part[1] + part[2] + part[3] + ob[0];
}

// ---------------- host launcher ----------------
extern "C" void kernel_launch(void* const* d_in, const int* in_sizes, int n_in,
                              void* d_out, int out_size) {
    const float* x     = (const float*)d_in[0];
    const int*   ei    = (const int*)d_in[1];
    const int*   ee    = (const int*)d_in[2];
    const float* pos   = (const float*)d_in[3];
    const float* eattr = (const float*)d_in[4];
    const int*   batch = (const int*)d_in[5];
    const float* lnW   = (const float*)d_in[6];
    const float* lnb   = (const float*)d_in[7];
    const float* Wi    = (const float*)d_in[8];
    const float* bi    = (const float*)d_in[9];
    const float* We    = (const float*)d_in[10];
    const float* be    = (const float*)d_in[11];
    const float* fcW   = (const float*)d_in[12];
    const float* fcb   = (const float*)d_in[13];
    const float* gam   = (const float*)d_in[14];
    const float* bet   = (const float*)d_in[15];
    const float* oW    = (const float*)d_in[16];
    const float* ob    = (const float*)d_in[17];
    float* out = (float*)d_out;

    static int smem_set = 0;
    if (!smem_set) {
        cudaFuncSetAttribute(k_trans, cudaFuncAttributeMaxDynamicSharedMemorySize, UPD_SMEM);
        smem_set = 1;
    }

    k_zero_pre<<<(NN + 255) / 256, 256>>>();
    k_linnode<<<NN / 8, 128>>>(x, lnW, lnb);
    k_deg<<<(EI + 255) / 256, 256>>>(ei, ee, pos);
    k_prepw<<<256, 256>>>(Wi, We);

    k_scan_a<<<NBLK_SCAN, 1024>>>(0);
    k_scan_a<<<NBLK_SCAN, 1024>>>(1);
    k_scan_b<<<1, 32>>>();
    k_scan_c<<<NBLK_SCAN, 1024>>>(0);
    k_scan_c<<<NBLK_SCAN, 1024>>>(1);
    k_fillf<<<(EI + 255) / 256, 256>>>(ei, ee, eattr);

    for (int l = 0; l < 4; l++) {
        k_trans<<<NBLK_UPD, 256, UPD_SMEM>>>(l, l & 1);
        k_gath2<<<(NN * 32 + 255) / 256, 256>>>(bi + l * HD, be + l * HD, batch, l & 1, l == 3);
    }

    k_fc<<<GB, 128>>>(fcW + 0 * HD * HD, fcb + 0 * HD, gam + 0 * HD, bet + 0 * HD, 0);
    k_fc<<<GB, 128>>>(fcW + 1 * HD * HD, fcb + 1 * HD, gam + 1 * HD, bet + 1 * HD, 1);
    k_fc<<<GB, 128>>>(fcW + 2 * HD * HD, fcb + 2 * HD, gam + 2 * HD, bet + 2 * HD, 0);
    k_out<<<GB, 128>>>(oW, ob, out);
}

// round 11
// speedup vs baseline: 2.5951x; 1.1045x over previous
#include <cuda_runtime.h>
#include <cuda_bf16.h>
#include <cuda_fp16.h>
#include <math.h>

#define NN 100000
#define NP 100096          // padded ( >= 1563*64 = 100032 )
#define NBLK_UPD 1563
#define EI 800000
#define EE 400000
#define HD 128
#define GB 256
#define ND 35
#define NBLK_SCAN 98       // ceil(100000/1024)

typedef unsigned long long ull;

// ---------------- device scratch ----------------
__device__ float d_h [NN * HD];
__device__ float d_h2[NN * HD];
__device__ float d_vp[NN * HD];
__device__ float d_vl[NN * HD];
__device__ unsigned d_yi[NP * HD / 2];   // h @ W_intra, fp16x2 packed
__device__ unsigned d_ye[NP * HD / 2];   // h @ W_inter, fp16x2 packed
__device__ float d_wint[EE];
__device__ int   d_ecnt_i[NN];
__device__ int   d_ecnt_e[NN];
__device__ int   d_fill_i[NN];
__device__ int   d_fill_e[NN];
__device__ int   d_off_i[NN + 1];
__device__ int   d_off_e[NN + 1];
__device__ int   d_bsum_i[NBLK_SCAN];
__device__ int   d_bsum_e[NBLK_SCAN];
__device__ int   d_csrc_i[EI];
__device__ float d_cw_i[EI];
__device__ int   d_csrc_e[EE];
__device__ float d_cw_e[EE];
__device__ float d_cnti[NN];
__device__ float d_cnte[NN];
__device__ float d_invi[NN];
__device__ float d_loge[NN];
__device__ float d_pool[GB * HD];
__device__ float d_fcbuf[GB * HD];
// weight image: bf16 hi/lo split, transposed [n][k] pairs packed in 32-bit words.
__device__ unsigned d_wimg[4 * 2 * 2 * 128 * 64];

// ---------------- helpers ----------------
__device__ __forceinline__ float siluf(float v) { return v / (1.0f + expf(-v)); }

__device__ __forceinline__ void red_add_v4(float* p, float4 v) {
    asm volatile("red.global.add.v4.f32 [%0], {%1,%2,%3,%4};"
                 :: "l"(p), "f"(v.x), "f"(v.y), "f"(v.z), "f"(v.w) : "memory");
}

// d = {hi=bf16(a1), lo=bf16(a0)}
__device__ __forceinline__ unsigned bf16x2_of(float a0, float a1) {
    unsigned w;
    asm("cvt.rn.bf16x2.f32 %0, %1, %2;" : "=r"(w) : "f"(a1), "f"(a0));
    return w;
}

// d = {hi=f16(a1), lo=f16(a0)}
__device__ __forceinline__ unsigned f16x2_of(float a0, float a1) {
    unsigned w;
    asm("cvt.rn.f16x2.f32 %0, %1, %2;" : "=r"(w) : "f"(a1), "f"(a0));
    return w;
}

__device__ __forceinline__ float2 f16x2_to_f2(unsigned w) {
    __half2 h = *(__half2*)&w;
    return __half22float2(h);
}

__device__ __forceinline__ void mma16816(float* d, const unsigned* a, const unsigned* b) {
    asm volatile("mma.sync.aligned.m16n8k16.row.col.f32.bf16.bf16.f32 "
                 "{%0,%1,%2,%3}, {%4,%5,%6,%7}, {%8,%9}, {%0,%1,%2,%3};"
                 : "+f"(d[0]), "+f"(d[1]), "+f"(d[2]), "+f"(d[3])
                 : "r"(a[0]), "r"(a[1]), "r"(a[2]), "r"(a[3]), "r"(b[0]), "r"(b[1]));
}

// ---------------- init ----------------
__global__ void k_zero_pre() {
    int i = blockIdx.x * blockDim.x + threadIdx.x;
    if (i < NN) {
        d_ecnt_i[i] = 0; d_ecnt_e[i] = 0;
        d_fill_i[i] = 0; d_fill_e[i] = 0;
    }
    if (i < GB * HD) d_pool[i] = 0.0f;
}

// lin_node: h = silu(x @ W + b)   (vp/vl NOT zeroed: layer 0 skips reading them)
__global__ __launch_bounds__(128) void k_linnode(const float* __restrict__ x,
                                                 const float* __restrict__ W,
                                                 const float* __restrict__ b) {
    __shared__ float Ws[ND * HD];
    __shared__ float xs[8][ND];
    int t = threadIdx.x;
    for (int i = t; i < ND * HD; i += 128) Ws[i] = W[i];
    int n0 = blockIdx.x * 8;
    for (int i = t; i < 8 * ND; i += 128) {
        int nn = i / ND, k = i % ND;
        xs[nn][k] = x[(n0 + nn) * ND + k];
    }
    __syncthreads();
    float bb = b[t];
    for (int nn = 0; nn < 8; nn++) {
        int n = n0 + nn;
        float acc = bb;
#pragma unroll
        for (int k = 0; k < ND; k++) acc += xs[nn][k] * Ws[k * HD + t];
        d_h[n * HD + t] = siluf(acc);
    }
}

// ---------------- degrees + geometric weights (merged) ----------------
__global__ void k_deg(const int* __restrict__ ei, const int* __restrict__ ee,
                      const float* __restrict__ pos) {
    int e = blockIdx.x * blockDim.x + threadIdx.x;
    if (e < EI) atomicAdd(&d_ecnt_i[ei[EI + e]], 1);
    if (e < EE) {
        int s = ee[e], d = ee[EE + e];
        float dx = pos[s * 3 + 0] - pos[d * 3 + 0];
        float dy = pos[s * 3 + 1] - pos[d * 3 + 1];
        float dz = pos[s * 3 + 2] - pos[d * 3 + 2];
        d_wint[e] = expf(-(dx * dx + dy * dy + dz * dz));
        atomicAdd(&d_ecnt_e[d], 1);
    }
}

// ---------------- prefix scan (exclusive) -> CSR offsets ----------------
__global__ __launch_bounds__(1024) void k_scan_a(int which) {
    __shared__ int sh[1024];
    const int* cnt = which ? d_ecnt_e : d_ecnt_i;
    int* off = which ? d_off_e : d_off_i;
    int* bs  = which ? d_bsum_e : d_bsum_i;
    int tid = threadIdx.x;
    int i = blockIdx.x * 1024 + tid;
    int v = (i < NN) ? cnt[i] : 0;
    sh[tid] = v;
    __syncthreads();
#pragma unroll
    for (int o = 1; o < 1024; o <<= 1) {
        int u = (tid >= o) ? sh[tid - o] : 0;
        __syncthreads();
        sh[tid] += u;
        __syncthreads();
    }
    if (i <= NN) off[i] = sh[tid] - v;  // exclusive
    if (tid == 1023) bs[blockIdx.x] = sh[1023];
}

__global__ void k_scan_b() {
    if (threadIdx.x == 0) {
        int r = 0;
        for (int b = 0; b < NBLK_SCAN; b++) { int t = d_bsum_i[b]; d_bsum_i[b] = r; r += t; }
    }
    if (threadIdx.x == 1) {
        int r = 0;
        for (int b = 0; b < NBLK_SCAN; b++) { int t = d_bsum_e[b]; d_bsum_e[b] = r; r += t; }
    }
}

__global__ __launch_bounds__(1024) void k_scan_c(int which) {
    int* off = which ? d_off_e : d_off_i;
    const int* bs = which ? d_bsum_e : d_bsum_i;
    int i = blockIdx.x * 1024 + threadIdx.x;
    if (i <= NN) off[i] += bs[blockIdx.x];
}

// ---------------- CSR fill + degree factors (merged) ----------------
__global__ void k_fillf(const int* __restrict__ ei, const int* __restrict__ ee,
                        const float* __restrict__ ea) {
    int e = blockIdx.x * blockDim.x + threadIdx.x;
    if (e < NN) {
        float ci = (float)d_ecnt_i[e];
        float ce = (float)d_ecnt_e[e];
        d_cnti[e] = ci;
        d_cnte[e] = ce;
        d_invi[e] = 1.0f / (ci + 1.0f);
        d_loge[e] = logf(ce + 1.0f);
    }
    if (e < EI) {
        int s = ei[e], d = ei[EI + e];
        int p = d_off_i[d] + atomicAdd(&d_fill_i[d], 1);
        d_csrc_i[p] = s;
        d_cw_i[p] = ea[e];
    }
    if (e < EE) {
        int s = ee[e], d = ee[EE + e];
        int p = d_off_e[d] + atomicAdd(&d_fill_e[d], 1);
        d_csrc_e[p] = s;
        d_cw_e[p] = d_wint[e];
    }
}

// ---------------- weight prep: transpose + bf16 hi/lo split (once) ----------------
__global__ void k_prepw(const float* __restrict__ Wi, const float* __restrict__ We) {
    int gid = blockIdx.x * blockDim.x + threadIdx.x;
    if (gid >= 65536) return;
    int j = gid & 63;            // k-pair word
    int n = (gid >> 6) & 127;    // output col = B n-row
    int m = (gid >> 13) & 1;
    int l = gid >> 14;
    const float* Wsrc = (m ? We : Wi) + l * HD * HD;
    int k0 = 2 * j;
    float w0 = Wsrc[k0 * HD + n];
    float w1 = Wsrc[(k0 + 1) * HD + n];
    unsigned wh = bf16x2_of(w0, w1);
    float r0 = w0 - __uint_as_float(wh << 16);
    float r1 = w1 - __uint_as_float(wh & 0xffff0000u);
    unsigned wl = bf16x2_of(r0, r1);
    int pb = l * 4 + m * 2;
    d_wimg[(size_t)pb * 8192 + n * 64 + j] = wh;
    d_wimg[(size_t)(pb + 1) * 8192 + n * 64 + j] = wl;
}

// ---------------- k_trans: dense dual GEMM yi = h@Wi, ye = h@We (bf16 x3 split) ----------------
#define AWOFF(mp) (256 + (mp) * 2304)
#define WWOFF(mp) (9472 + (mp) * 4608)
#define UPD_SMEM 111616

__global__ __launch_bounds__(256, 2)
void k_trans(int layer, int parity) {
    extern __shared__ unsigned swm[];
    int t = threadIdx.x, lane = t & 31, wid = t >> 5;
    int n0 = blockIdx.x * 64;
    const float* __restrict__ hin = parity ? d_h2 : d_h;

    float acc_i[8][4], acc_e[8][4];
#pragma unroll
    for (int tt = 0; tt < 8; tt++)
#pragma unroll
        for (int q = 0; q < 4; q++) { acc_i[tt][q] = 0.f; acc_e[tt][q] = 0.f; }

    int strip = wid >> 1, half = wid & 1;
    int row = t >> 2, seg = t & 3;
    unsigned arowb = (unsigned)((strip * 16 + (lane >> 2)) * 36 + (lane & 3));
    unsigned browb = (unsigned)((half * 64 + (lane >> 2)) * 36 + (lane & 3));
    int nclamp = n0 + row < NN ? n0 + row : NN - 1;   // clamp tail rows (results discarded)

    for (int c = 0; c < 2; c++) {
        __syncthreads();
        // ---- stage A: fp32 h -> bf16 hi/lo ----
        {
            const float* src = hin + (size_t)nclamp * HD + c * 64 + seg * 16;
            unsigned hb = AWOFF(0) + row * 36 + seg * 8;
            unsigned lb = AWOFF(1) + row * 36 + seg * 8;
#pragma unroll
            for (int q = 0; q < 4; q++) {
                float4 v = ((const float4*)src)[q];
                unsigned wh0 = bf16x2_of(v.x, v.y);
                float r0 = v.x - __uint_as_float(wh0 << 16);
                float r1 = v.y - __uint_as_float(wh0 & 0xffff0000u);
                unsigned wl0 = bf16x2_of(r0, r1);
                unsigned wh1 = bf16x2_of(v.z, v.w);
                float r2 = v.z - __uint_as_float(wh1 << 16);
                float r3 = v.w - __uint_as_float(wh1 & 0xffff0000u);
                unsigned wl1 = bf16x2_of(r2, r3);
                swm[hb + q * 2]     = wh0;
                swm[hb + q * 2 + 1] = wh1;
                swm[lb + q * 2]     = wl0;
                swm[lb + q * 2 + 1] = wl1;
            }
        }
        // ---- stage W: copy prepped image chunk ----
#pragma unroll
        for (int mp = 0; mp < 4; mp++) {
            unsigned pbase = (unsigned)(layer * 4 + mp) * 8192 + c * 32;
#pragma unroll
            for (int uu = 0; uu < 4; uu++) {
                int u = t + uu * 256;
                int nrow = u >> 3, s = u & 7;
                int4 v = *(const int4*)(d_wimg + pbase + nrow * 64 + s * 4);
                *(int4*)(swm + WWOFF(mp) + nrow * 36 + s * 4) = v;
            }
        }
        __syncthreads();
        // ---- compute: 4 k-steps of 16 ----
#pragma unroll
        for (int s = 0; s < 4; s++) {
            unsigned ko = s * 8;
            unsigned a_h[4], a_l[4];
            a_h[0] = swm[AWOFF(0) + arowb + ko];
            a_h[1] = swm[AWOFF(0) + arowb + 288 + ko];
            a_h[2] = swm[AWOFF(0) + arowb + ko + 4];
            a_h[3] = swm[AWOFF(0) + arowb + 288 + ko + 4];
            a_l[0] = swm[AWOFF(1) + arowb + ko];
            a_l[1] = swm[AWOFF(1) + arowb + 288 + ko];
            a_l[2] = swm[AWOFF(1) + arowb + ko + 4];
            a_l[3] = swm[AWOFF(1) + arowb + 288 + ko + 4];
#pragma unroll
            for (int tt = 0; tt < 8; tt++) {
                unsigned bo = browb + tt * 288 + ko;
                unsigned bb[2];
                bb[0] = swm[WWOFF(0) + bo]; bb[1] = swm[WWOFF(0) + bo + 4];
                mma16816(acc_i[tt], a_h, bb);
                mma16816(acc_i[tt], a_l, bb);
                bb[0] = swm[WWOFF(1) + bo]; bb[1] = swm[WWOFF(1) + bo + 4];
                mma16816(acc_i[tt], a_h, bb);
                bb[0] = swm[WWOFF(2) + bo]; bb[1] = swm[WWOFF(2) + bo + 4];
                mma16816(acc_e[tt], a_h, bb);
                mma16816(acc_e[tt], a_l, bb);
                bb[0] = swm[WWOFF(3) + bo]; bb[1] = swm[WWOFF(3) + bo + 4];
                mma16816(acc_e[tt], a_h, bb);
            }
        }
    }

    // ---- store yi/ye as fp16x2 words (padded arrays: rows up to NP safe) ----
#pragma unroll
    for (int rr = 0; rr < 2; rr++) {
        int n = n0 + strip * 16 + (lane >> 2) + rr * 8;
#pragma unroll
        for (int tt = 0; tt < 8; tt++) {
            int cc = half * 64 + tt * 8 + (lane & 3) * 2;
            size_t woff = (size_t)n * 64 + (cc >> 1);
            d_yi[woff] = f16x2_of(acc_i[tt][rr * 2], acc_i[tt][rr * 2 + 1]);
            d_ye[woff] = f16x2_of(acc_e[tt][rr * 2], acc_e[tt][rr * 2 + 1]);
        }
    }
}

// ---------------- k_gath2: CSR gather of fp16 yi/ye + full epilogue ----------------
__global__ __launch_bounds__(256) void k_gath2(const float* __restrict__ bi,
                                               const float* __restrict__ be,
                                               const int* __restrict__ batch,
                                               int parity, int first, int last) {
    int g = blockIdx.x * 256 + threadIdx.x;
    int n = g >> 5;
    int lane = g & 31;
    if (n >= NN) return;
    const float* __restrict__ hin = parity ? d_h2 : d_h;
    float* hout = parity ? d_h : d_h2;

    float4 si, se;
    // intra gather from yi (lane covers cols lane*4..lane*4+3 -> uint2 per row)
    {
        int p = d_off_i[n], pe = d_off_i[n + 1];
        float4 a0 = {0, 0, 0, 0}, a1 = {0, 0, 0, 0};
        for (; p + 4 <= pe; p += 4) {
            int s0 = __ldg(d_csrc_i + p);
            int s1 = __ldg(d_csrc_i + p + 1);
            int s2 = __ldg(d_csrc_i + p + 2);
            int s3 = __ldg(d_csrc_i + p + 3);
            float w0 = __ldg(d_cw_i + p);
            float w1 = __ldg(d_cw_i + p + 1);
            float w2 = __ldg(d_cw_i + p + 2);
            float w3 = __ldg(d_cw_i + p + 3);
            uint2 y0 = *(const uint2*)(d_yi + (size_t)s0 * 64 + lane * 2);
            uint2 y1 = *(const uint2*)(d_yi + (size_t)s1 * 64 + lane * 2);
            uint2 y2 = *(const uint2*)(d_yi + (size_t)s2 * 64 + lane * 2);
            uint2 y3 = *(const uint2*)(d_yi + (size_t)s3 * 64 + lane * 2);
            float2 f0a = f16x2_to_f2(y0.x), f0b = f16x2_to_f2(y0.y);
            float2 f1a = f16x2_to_f2(y1.x), f1b = f16x2_to_f2(y1.y);
            float2 f2a = f16x2_to_f2(y2.x), f2b = f16x2_to_f2(y2.y);
            float2 f3a = f16x2_to_f2(y3.x), f3b = f16x2_to_f2(y3.y);
            a0.x += f0a.x * w0; a0.y += f0a.y * w0; a0.z += f0b.x * w0; a0.w += f0b.y * w0;
            a1.x += f1a.x * w1; a1.y += f1a.y * w1; a1.z += f1b.x * w1; a1.w += f1b.y * w1;
            a0.x += f2a.x * w2; a0.y += f2a.y * w2; a0.z += f2b.x * w2; a0.w += f2b.y * w2;
            a1.x += f3a.x * w3; a1.y += f3a.y * w3; a1.z += f3b.x * w3; a1.w += f3b.y * w3;
        }
        for (; p < pe; p++) {
            int s0 = __ldg(d_csrc_i + p);
            float w0 = __ldg(d_cw_i + p);
            uint2 y0 = *(const uint2*)(d_yi + (size_t)s0 * 64 + lane * 2);
            float2 f0a = f16x2_to_f2(y0.x), f0b = f16x2_to_f2(y0.y);
            a0.x += f0a.x * w0; a0.y += f0a.y * w0; a0.z += f0b.x * w0; a0.w += f0b.y * w0;
        }
        si = make_float4(a0.x + a1.x, a0.y + a1.y, a0.z + a1.z, a0.w + a1.w);
    }
    // inter gather from ye
    {
        int p = d_off_e[n], pe = d_off_e[n + 1];
        float4 a0 = {0, 0, 0, 0}, a1 = {0, 0, 0, 0};
        for (; p + 4 <= pe; p += 4) {
            int s0 = __ldg(d_csrc_e + p);
            int s1 = __ldg(d_csrc_e + p + 1);
            int s2 = __ldg(d_csrc_e + p + 2);
            int s3 = __ldg(d_csrc_e + p + 3);
            float w0 = __ldg(d_cw_e + p);
            float w1 = __ldg(d_cw_e + p + 1);
            float w2 = __ldg(d_cw_e + p + 2);
            float w3 = __ldg(d_cw_e + p + 3);
            uint2 y0 = *(const uint2*)(d_ye + (size_t)s0 * 64 + lane * 2);
            uint2 y1 = *(const uint2*)(d_ye + (size_t)s1 * 64 + lane * 2);
            uint2 y2 = *(const uint2*)(d_ye + (size_t)s2 * 64 + lane * 2);
            uint2 y3 = *(const uint2*)(d_ye + (size_t)s3 * 64 + lane * 2);
            float2 f0a = f16x2_to_f2(y0.x), f0b = f16x2_to_f2(y0.y);
            float2 f1a = f16x2_to_f2(y1.x), f1b = f16x2_to_f2(y1.y);
            float2 f2a = f16x2_to_f2(y2.x), f2b = f16x2_to_f2(y2.y);
            float2 f3a = f16x2_to_f2(y3.x), f3b = f16x2_to_f2(y3.y);
            a0.x += f0a.x * w0; a0.y += f0a.y * w0; a0.z += f0b.x * w0; a0.w += f0b.y * w0;
            a1.x += f1a.x * w1; a1.y += f1a.y * w1; a1.z += f1b.x * w1; a1.w += f1b.y * w1;
            a0.x += f2a.x * w2; a0.y += f2a.y * w2; a0.z += f2b.x * w2; a0.w += f2b.y * w2;
            a1.x += f3a.x * w3; a1.y += f3a.y * w3; a1.z += f3b.x * w3; a1.w += f3b.y * w3;
        }
        for (; p < pe; p++) {
            int s0 = __ldg(d_csrc_e + p);
            float w0 = __ldg(d_cw_e + p);
            uint2 y0 = *(const uint2*)(d_ye + (size_t)s0 * 64 + lane * 2);
            float2 f0a = f16x2_to_f2(y0.x), f0b = f16x2_to_f2(y0.y);
            a0.x += f0a.x * w0; a0.y += f0a.y * w0; a0.z += f0b.x * w0; a0.w += f0b.y * w0;
        }
        se = make_float4(a0.x + a1.x, a0.y + a1.y, a0.z + a1.z, a0.w + a1.w);
    }

    // epilogue
    float ci = __ldg(d_cnti + n), inv = __ldg(d_invi + n);
    float ce = __ldg(d_cnte + n), lge = __ldg(d_loge + n);
    float4 bi4 = *(const float4*)(bi + lane * 4);
    float4 be4 = *(const float4*)(be + lane * 4);
    size_t off = (size_t)n * HD + lane * 4;
    float4 vp, vl;
    if (first) {
        vp = make_float4(0.f, 0.f, 0.f, 0.f);
        vl = make_float4(0.f, 0.f, 0.f, 0.f);
    } else {
        vp = *(const float4*)(d_vp + off);
        vl = *(const float4*)(d_vl + off);
    }
    float4 hh = *(const float4*)(hin + off);

    float p0 = siluf((si.x + ci * bi4.x) * inv + vp.x);
    float p1 = siluf((si.y + ci * bi4.y) * inv + vp.y);
    float p2 = siluf((si.z + ci * bi4.z) * inv + vp.z);
    float p3 = siluf((si.w + ci * bi4.w) * inv + vp.w);
    float l0 = siluf((se.x + ce * be4.x) * lge + vl.x);
    float l1 = siluf((se.y + ce * be4.y) * lge + vl.y);
    float l2 = siluf((se.z + ce * be4.z) * lge + vl.z);
    float l3 = siluf((se.w + ce * be4.w) * lge + vl.w);
    float4 ho = make_float4(hh.x + p0 + l0, hh.y + p1 + l1, hh.z + p2 + l2, hh.w + p3 + l3);

    if (!last) {
        *(float4*)(d_vp + off) = make_float4(p0, p1, p2, p3);
        *(float4*)(d_vl + off) = make_float4(l0, l1, l2, l3);
        *(float4*)(hout + off) = ho;
    } else {
        int bb = __ldg(batch + n);
        red_add_v4(d_pool + bb * HD + lane * 4, ho);
    }
}

// ---------------- FC head ----------------
__global__ __launch_bounds__(128) void k_fc(const float* __restrict__ W,
                                            const float* __restrict__ b,
                                            const float* __restrict__ gam,
                                            const float* __restrict__ bet,
                                            int swap) {
    __shared__ float gr[HD];
    int bid = blockIdx.x;
    int t = threadIdx.x;
    const float* gin = swap ? d_fcbuf : d_pool;
    float* gout = swap ? d_pool : d_fcbuf;
    gr[t] = gin[bid * HD + t];
    __syncthreads();
    float acc = b[t];
#pragma unroll 8
    for (int k = 0; k < HD; k++) acc += gr[k] * W[k * HD + t];
    acc = acc > 0.f ? acc : 0.01f * acc;
    float bnscale = rsqrtf(1.0f + 1e-5f);
    acc = acc * bnscale * gam[t] + bet[t];
    gout[bid * HD + t] = acc;
}

__global__ __launch_bounds__(128) void k_out(const float* __restrict__ oW,
                                             const float* __restrict__ ob,
                                             float* __restrict__ out) {
    __shared__ float part[4];
    int b = blockIdx.x;
    int t = threadIdx.x;
    float p = d_fcbuf[b * HD + t] * oW[t];
#pragma unroll
    for (int o = 16; o > 0; o >>= 1) p += __shfl_down_sync(0xffffffffu, p, o);
    if ((t & 31) == 0) part[t >> 5] = p;
    __syncthreads();
    if (t == 0) out[b] = part[0] + part[1] + part[2] + part[3] + ob[0];
}

// ---------------- host launcher ----------------
extern "C" void kernel_launch(void* const* d_in, const int* in_sizes, int n_in,
                              void* d_out, int out_size) {
    const float* x     = (const float*)d_in[0];
    const int*   ei    = (const int*)d_in[1];
    const int*   ee    = (const int*)d_in[2];
    const float* pos   = (const float*)d_in[3];
    const float* eattr = (const float*)d_in[4];
    const int*   batch = (const int*)d_in[5];
    const float* lnW   = (const float*)d_in[6];
    const float* lnb   = (const float*)d_in[7];
    const float* Wi    = (const float*)d_in[8];
    const float* bi    = (const float*)d_in[9];
    const float* We    = (const float*)d_in[10];
    const float* be    = (const float*)d_in[11];
    const float* fcW   = (const float*)d_in[12];
    const float* fcb   = (const float*)d_in[13];
    const float* gam   = (const float*)d_in[14];
    const float* bet   = (const float*)d_in[15];
    const float* oW    = (const float*)d_in[16];
    const float* ob    = (const float*)d_in[17];
    float* out = (float*)d_out;

    static int smem_set = 0;
    if (!smem_set) {
        cudaFuncSetAttribute(k_trans, cudaFuncAttributeMaxDynamicSharedMemorySize, UPD_SMEM);
        smem_set = 1;
    }

    k_zero_pre<<<(NN + 255) / 256, 256>>>();
    k_linnode<<<NN / 8, 128>>>(x, lnW, lnb);
    k_deg<<<(EI + 255) / 256, 256>>>(ei, ee, pos);
    k_prepw<<<256, 256>>>(Wi, We);

    k_scan_a<<<NBLK_SCAN, 1024>>>(0);
    k_scan_a<<<NBLK_SCAN, 1024>>>(1);
    k_scan_b<<<1, 32>>>();
    k_scan_c<<<NBLK_SCAN, 1024>>>(0);
    k_scan_c<<<NBLK_SCAN, 1024>>>(1);
    k_fillf<<<(EI + 255) / 256, 256>>>(ei, ee, eattr);

    for (int l = 0; l < 4; l++) {
        k_trans<<<NBLK_UPD, 256, UPD_SMEM>>>(l, l & 1);
        k_gath2<<<(NN * 32 + 255) / 256, 256>>>(bi + l * HD, be + l * HD, batch,
                                                l & 1, l == 0, l == 3);
    }

    k_fc<<<GB, 128>>>(fcW + 0 * HD * HD, fcb + 0 * HD, gam + 0 * HD, bet + 0 * HD, 0);
    k_fc<<<GB, 128>>>(fcW + 1 * HD * HD, fcb + 1 * HD, gam + 1 * HD, bet + 1 * HD, 1);
    k_fc<<<GB, 128>>>(fcW + 2 * HD * HD, fcb + 2 * HD, gam + 2 * HD, bet + 2 * HD, 0);
    k_out<<<GB, 128>>>(oW, ob, out);
}